// round 2
// baseline (speedup 1.0000x reference)
#include <cuda_runtime.h>
#include <cstdint>

// Problem constants
#define Bn  2
#define Sn  2048
#define En  2048
#define Hn  16
#define Dn  128
#define NEn 8
#define Rn  16
#define HDn 2048
#define Mn  4096            // B*S
#define NEG_BIG -3.0e38f

// ---------------- scratch (device globals: no cudaMalloc allowed) ----------
__device__ float g_q[(size_t)Mn * HDn];
__device__ float g_k[(size_t)Mn * HDn];
__device__ float g_v[(size_t)Mn * HDn];
__device__ float g_o[(size_t)Mn * HDn];
__device__ float g_h[(size_t)Mn * (NEn * Rn)];

// ---------------------------------------------------------------------------
// gemm128: C[M,N] = A[M,K] @ B[N,K]^T (+bias[n]) (+C if accFlag)
// BM=BN=128, BK=16, 256 threads, 8x8 microtile
// ---------------------------------------------------------------------------
__global__ void __launch_bounds__(256) gemm128_kernel(
    const float* __restrict__ A, const float* __restrict__ Bm,
    const float* __restrict__ bias, float* __restrict__ C,
    int M, int N, int K, int accFlag)
{
    __shared__ float As[16][132];
    __shared__ float Bs[16][132];
    const int bm = blockIdx.y * 128;
    const int bn = blockIdx.x * 128;
    const int tid = threadIdx.x;
    const int tx = tid & 15;
    const int ty = tid >> 4;
    const int lr = tid >> 2;          // 0..63
    const int lk = (tid & 3) << 2;    // 0,4,8,12

    float acc[8][8];
#pragma unroll
    for (int i = 0; i < 8; i++)
#pragma unroll
        for (int j = 0; j < 8; j++) acc[i][j] = 0.f;

    const float* Aptr = A + (size_t)(bm + lr) * K + lk;
    const float* Bptr = Bm + (size_t)(bn + lr) * K + lk;

    for (int k0 = 0; k0 < K; k0 += 16) {
#pragma unroll
        for (int i = 0; i < 2; i++) {
            float4 a = *(const float4*)(Aptr + (size_t)i * 64 * K + k0);
            As[lk + 0][lr + i * 64] = a.x;
            As[lk + 1][lr + i * 64] = a.y;
            As[lk + 2][lr + i * 64] = a.z;
            As[lk + 3][lr + i * 64] = a.w;
            float4 b = *(const float4*)(Bptr + (size_t)i * 64 * K + k0);
            Bs[lk + 0][lr + i * 64] = b.x;
            Bs[lk + 1][lr + i * 64] = b.y;
            Bs[lk + 2][lr + i * 64] = b.z;
            Bs[lk + 3][lr + i * 64] = b.w;
        }
        __syncthreads();
#pragma unroll
        for (int kk = 0; kk < 16; kk++) {
            float4 a0 = *(const float4*)&As[kk][ty * 8];
            float4 a1 = *(const float4*)&As[kk][ty * 8 + 4];
            float4 b0 = *(const float4*)&Bs[kk][tx * 8];
            float4 b1 = *(const float4*)&Bs[kk][tx * 8 + 4];
            float ar[8] = {a0.x, a0.y, a0.z, a0.w, a1.x, a1.y, a1.z, a1.w};
            float br[8] = {b0.x, b0.y, b0.z, b0.w, b1.x, b1.y, b1.z, b1.w};
#pragma unroll
            for (int i = 0; i < 8; i++)
#pragma unroll
                for (int j = 0; j < 8; j++)
                    acc[i][j] = fmaf(ar[i], br[j], acc[i][j]);
        }
        __syncthreads();
    }

#pragma unroll
    for (int i = 0; i < 8; i++) {
        int m = bm + ty * 8 + i;
#pragma unroll
        for (int jv = 0; jv < 2; jv++) {
            int n = bn + tx * 8 + jv * 4;
            float4 v = make_float4(acc[i][jv * 4 + 0], acc[i][jv * 4 + 1],
                                   acc[i][jv * 4 + 2], acc[i][jv * 4 + 3]);
            if (bias) {
                float4 bb = *(const float4*)&bias[n];
                v.x += bb.x; v.y += bb.y; v.z += bb.z; v.w += bb.w;
            }
            if (accFlag) {
                float4 c0 = *(const float4*)&C[(size_t)m * N + n];
                v.x += c0.x; v.y += c0.y; v.z += c0.z; v.w += c0.w;
            }
            *(float4*)&C[(size_t)m * N + n] = v;
        }
    }
}

// ---------------------------------------------------------------------------
// gemm64: C[M,N] = (A[M,K] @ B[N,K]^T) * mask  (mask broadcast over R=16)
// used for the low-rank h projections (N = NE*R = 128)
// BM=BN=64, BK=16, 256 threads, 4x4 microtile
// ---------------------------------------------------------------------------
__global__ void __launch_bounds__(256) gemm64_kernel(
    const float* __restrict__ A, const float* __restrict__ Bm,
    const float* __restrict__ mask, float* __restrict__ C,
    int M, int N, int K)
{
    __shared__ float As[16][68];
    __shared__ float Bs[16][68];
    const int bm = blockIdx.y * 64;
    const int bn = blockIdx.x * 64;
    const int tid = threadIdx.x;
    const int tx = tid & 15;
    const int ty = tid >> 4;
    const int lr = tid >> 2;          // 0..63
    const int lk = (tid & 3) << 2;    // 0,4,8,12

    float acc[4][4];
#pragma unroll
    for (int i = 0; i < 4; i++)
#pragma unroll
        for (int j = 0; j < 4; j++) acc[i][j] = 0.f;

    const float* Aptr = A + (size_t)(bm + lr) * K + lk;
    const float* Bptr = Bm + (size_t)(bn + lr) * K + lk;

    for (int k0 = 0; k0 < K; k0 += 16) {
        float4 a = *(const float4*)(Aptr + k0);
        As[lk + 0][lr] = a.x; As[lk + 1][lr] = a.y;
        As[lk + 2][lr] = a.z; As[lk + 3][lr] = a.w;
        float4 b = *(const float4*)(Bptr + k0);
        Bs[lk + 0][lr] = b.x; Bs[lk + 1][lr] = b.y;
        Bs[lk + 2][lr] = b.z; Bs[lk + 3][lr] = b.w;
        __syncthreads();
#pragma unroll
        for (int kk = 0; kk < 16; kk++) {
            float4 av = *(const float4*)&As[kk][ty * 4];
            float4 bv = *(const float4*)&Bs[kk][tx * 4];
            float ar[4] = {av.x, av.y, av.z, av.w};
            float br[4] = {bv.x, bv.y, bv.z, bv.w};
#pragma unroll
            for (int i = 0; i < 4; i++)
#pragma unroll
                for (int j = 0; j < 4; j++)
                    acc[i][j] = fmaf(ar[i], br[j], acc[i][j]);
        }
        __syncthreads();
    }

#pragma unroll
    for (int i = 0; i < 4; i++) {
        int m = bm + ty * 4 + i;
        int n = bn + tx * 4;
        float sc = mask[(size_t)m * NEn + (n >> 4)];  // n..n+3 share the same ne (R=16)
        float4 v = make_float4(acc[i][0] * sc, acc[i][1] * sc,
                               acc[i][2] * sc, acc[i][3] * sc);
        *(float4*)&C[(size_t)m * N + n] = v;
    }
}

// ---------------------------------------------------------------------------
// RoPE (in-place on q and k).  layout [B,S,H,D]; pair (i, i+64)
// ---------------------------------------------------------------------------
__global__ void rope_kernel(float* __restrict__ q, float* __restrict__ k)
{
    const int total = Bn * Sn * Hn * (Dn / 2);   // 4,194,304
    int idx = blockIdx.x * blockDim.x + threadIdx.x;
    if (idx >= total) return;
    int i = idx & 63;
    int s = (idx >> 10) & (Sn - 1);
    // inv_freq = 10000^(-i/64), computed in double then rounded (matches fp32 ref to ~1 ulp)
    float inv = (float)exp(-(double)i * 0.14391156831212788);  // ln(10000)/64
    float ang = (float)s * inv;
    float c, sn;
    sincosf(ang, &sn, &c);
    size_t base = ((size_t)(idx >> 6)) * 128;  // (b,s,h) flattened * D
    float q0 = q[base + i], q1 = q[base + i + 64];
    q[base + i]      = q0 * c - q1 * sn;
    q[base + i + 64] = q1 * c + q0 * sn;
    float k0 = k[base + i], k1 = k[base + i + 64];
    k[base + i]      = k0 * c - k1 * sn;
    k[base + i + 64] = k1 * c + k0 * sn;
}

// ---------------------------------------------------------------------------
// Flash attention, fp32. grid (S/64, H, B), 256 threads.
// Q/K stored d-major in smem ([128][64+4]) for conflict-free float4 frags.
// Online softmax; O accumulator in registers (32 floats/thread).
// ---------------------------------------------------------------------------
#define FLASH_SMEM_FLOATS (2 * 128 * 68 + 64 * 132 + 64 * 68 + 3 * 64)
#define FLASH_SMEM_BYTES  (FLASH_SMEM_FLOATS * 4)

__global__ void __launch_bounds__(256) flash_kernel(
    const float* __restrict__ Q, const float* __restrict__ K,
    const float* __restrict__ V, float* __restrict__ O)
{
    extern __shared__ float sm[];
    float (*Qs)[68]  = (float(*)[68])sm;                             // [128][68]
    float (*Ks)[68]  = (float(*)[68])(sm + 128 * 68);                // [128][68]
    float (*Vs)[132] = (float(*)[132])(sm + 2 * 128 * 68);           // [64][132]
    float (*Ps)[68]  = (float(*)[68])(sm + 2 * 128 * 68 + 64 * 132); // [64][68]
    float* m_s    = sm + 2 * 128 * 68 + 64 * 132 + 64 * 68;
    float* l_s    = m_s + 64;
    float* corr_s = l_s + 64;

    const int q0 = blockIdx.x * 64;
    const int h  = blockIdx.y;
    const int b  = blockIdx.z;
    const int tid = threadIdx.x;
    const int tx = tid & 15, ty = tid >> 4;
    const int r4 = tid >> 2;     // 0..63
    const int c4 = tid & 3;      // 0..3

    const float scale = 0.08838834764831845f;  // 1/sqrt(128)

    // load Q tile (pre-scaled), transposed to [d][row]
    {
        const float4* src = (const float4*)(Q + ((((size_t)b * Sn + q0 + r4) * Hn + h) << 7));
#pragma unroll
        for (int f = 0; f < 8; f++) {
            int fi = c4 * 8 + f;
            float4 v = src[fi];
            int d = fi * 4;
            Qs[d + 0][r4] = v.x * scale;
            Qs[d + 1][r4] = v.y * scale;
            Qs[d + 2][r4] = v.z * scale;
            Qs[d + 3][r4] = v.w * scale;
        }
    }
    if (tid < 64) { m_s[tid] = NEG_BIG; l_s[tid] = 0.f; }

    float4 oa[8];
#pragma unroll
    for (int f = 0; f < 8; f++) oa[f] = make_float4(0.f, 0.f, 0.f, 0.f);

    for (int j0 = 0; j0 <= q0; j0 += 64) {
        __syncthreads();   // protect Ks/Vs/Ps from previous iter's consumers; also covers Q load
        {
            const float* kb = K + ((((size_t)b * Sn + j0 + r4) * Hn + h) << 7);
            const float* vb = V + ((((size_t)b * Sn + j0 + r4) * Hn + h) << 7);
            const float4* ks = (const float4*)kb;
            const float4* vs = (const float4*)vb;
            float4* vrow = (float4*)&Vs[r4][0];
#pragma unroll
            for (int f = 0; f < 8; f++) {
                int fi = c4 * 8 + f;
                float4 kv = ks[fi];
                int d = fi * 4;
                Ks[d + 0][r4] = kv.x;
                Ks[d + 1][r4] = kv.y;
                Ks[d + 2][r4] = kv.z;
                Ks[d + 3][r4] = kv.w;
                vrow[fi] = vs[fi];
            }
        }
        __syncthreads();

        // scores: 4x4 per thread
        float s[4][4];
#pragma unroll
        for (int i = 0; i < 4; i++)
#pragma unroll
            for (int j = 0; j < 4; j++) s[i][j] = 0.f;

        for (int d = 0; d < 128; d++) {
            float4 qv = *(const float4*)&Qs[d][ty * 4];
            float4 kv = *(const float4*)&Ks[d][tx * 4];
            float qa[4] = {qv.x, qv.y, qv.z, qv.w};
            float ka[4] = {kv.x, kv.y, kv.z, kv.w};
#pragma unroll
            for (int i = 0; i < 4; i++)
#pragma unroll
                for (int j = 0; j < 4; j++)
                    s[i][j] = fmaf(qa[i], ka[j], s[i][j]);
        }

        if (j0 == q0) {   // diagonal tile: causal mask
#pragma unroll
            for (int i = 0; i < 4; i++)
#pragma unroll
                for (int j = 0; j < 4; j++)
                    if (ty * 4 + i < tx * 4 + j) s[i][j] = NEG_BIG;
        }

        // row max -> m_s / corr_s   (reduce over the 16-lane tx group)
#pragma unroll
        for (int i = 0; i < 4; i++) {
            float rm = fmaxf(fmaxf(s[i][0], s[i][1]), fmaxf(s[i][2], s[i][3]));
#pragma unroll
            for (int off = 8; off > 0; off >>= 1)
                rm = fmaxf(rm, __shfl_xor_sync(0xffffffffu, rm, off));
            if (tx == 0) {
                int row = ty * 4 + i;
                float mo = m_s[row];
                float mn = fmaxf(mo, rm);
                m_s[row] = mn;
                corr_s[row] = __expf(mo - mn);
            }
        }
        __syncthreads();

        // probs -> Ps, row sums -> l_s
#pragma unroll
        for (int i = 0; i < 4; i++) {
            int row = ty * 4 + i;
            float mn = m_s[row];
            float rs = 0.f;
#pragma unroll
            for (int j = 0; j < 4; j++) {
                float p = __expf(s[i][j] - mn);
                Ps[row][tx * 4 + j] = p;
                rs += p;
            }
#pragma unroll
            for (int off = 8; off > 0; off >>= 1)
                rs += __shfl_xor_sync(0xffffffffu, rs, off);
            if (tx == 0) l_s[row] = l_s[row] * corr_s[row] + rs;
        }
        __syncthreads();

        // O update: rescale and accumulate P @ V
        {
            float cr = corr_s[r4];
#pragma unroll
            for (int f = 0; f < 8; f++) {
                oa[f].x *= cr; oa[f].y *= cr; oa[f].z *= cr; oa[f].w *= cr;
            }
            for (int j = 0; j < 64; j++) {
                float p = Ps[r4][j];
                const float4* vrow = (const float4*)&Vs[j][0];
#pragma unroll
                for (int f = 0; f < 8; f++) {
                    float4 v = vrow[c4 + 4 * f];
                    oa[f].x = fmaf(p, v.x, oa[f].x);
                    oa[f].y = fmaf(p, v.y, oa[f].y);
                    oa[f].z = fmaf(p, v.z, oa[f].z);
                    oa[f].w = fmaf(p, v.w, oa[f].w);
                }
            }
        }
    }

    // finalize
    {
        float invl = 1.f / l_s[r4];
        float4* dst = (float4*)(O + ((((size_t)b * Sn + q0 + r4) * Hn + h) << 7));
#pragma unroll
        for (int f = 0; f < 8; f++) {
            float4 v = oa[f];
            v.x *= invl; v.y *= invl; v.z *= invl; v.w *= invl;
            dst[c4 + 4 * f] = v;
        }
    }
}

// ---------------------------------------------------------------------------
extern "C" void kernel_launch(void* const* d_in, const int* in_sizes, int n_in,
                              void* d_out, int out_size)
{
    const float* x    = (const float*)d_in[0];
    const float* mask = (const float*)d_in[1];
    const float* Wq = (const float*)d_in[2];
    const float* bq = (const float*)d_in[3];
    const float* Aq = (const float*)d_in[4];
    const float* Bq = (const float*)d_in[5];
    const float* Wk = (const float*)d_in[6];
    const float* bk = (const float*)d_in[7];
    const float* Ak = (const float*)d_in[8];
    const float* Bk = (const float*)d_in[9];
    const float* Wv = (const float*)d_in[10];
    const float* bv = (const float*)d_in[11];
    const float* Av = (const float*)d_in[12];
    const float* Bv = (const float*)d_in[13];
    const float* Wo = (const float*)d_in[14];
    const float* bo = (const float*)d_in[15];
    const float* Ao = (const float*)d_in[16];
    const float* Bo = (const float*)d_in[17];
    float* out = (float*)d_out;

    float *gq, *gk, *gv, *go, *gh;
    cudaGetSymbolAddress((void**)&gq, g_q);
    cudaGetSymbolAddress((void**)&gk, g_k);
    cudaGetSymbolAddress((void**)&gv, g_v);
    cudaGetSymbolAddress((void**)&go, g_o);
    cudaGetSymbolAddress((void**)&gh, g_h);

    dim3 g128(HDn / 128, Mn / 128);         // (16, 32)
    dim3 g64h((NEn * Rn) / 64, Mn / 64);    // (2, 64)

    // ---- Q ----
    gemm64_kernel<<<g64h, 256>>>(x, Aq, mask, gh, Mn, NEn * Rn, En);
    gemm128_kernel<<<g128, 256>>>(x, Wq, bq, gq, Mn, HDn, En, 0);
    gemm128_kernel<<<g128, 256>>>(gh, Bq, nullptr, gq, Mn, HDn, NEn * Rn, 1);
    // ---- K ----
    gemm64_kernel<<<g64h, 256>>>(x, Ak, mask, gh, Mn, NEn * Rn, En);
    gemm128_kernel<<<g128, 256>>>(x, Wk, bk, gk, Mn, HDn, En, 0);
    gemm128_kernel<<<g128, 256>>>(gh, Bk, nullptr, gk, Mn, HDn, NEn * Rn, 1);
    // ---- V ----
    gemm64_kernel<<<g64h, 256>>>(x, Av, mask, gh, Mn, NEn * Rn, En);
    gemm128_kernel<<<g128, 256>>>(x, Wv, bv, gv, Mn, HDn, En, 0);
    gemm128_kernel<<<g128, 256>>>(gh, Bv, nullptr, gv, Mn, HDn, NEn * Rn, 1);

    // ---- RoPE on q, k ----
    {
        int total = Bn * Sn * Hn * (Dn / 2);
        rope_kernel<<<(total + 255) / 256, 256>>>(gq, gk);
    }

    // ---- Attention ----
    cudaFuncSetAttribute(flash_kernel, cudaFuncAttributeMaxDynamicSharedMemorySize,
                         FLASH_SMEM_BYTES);
    flash_kernel<<<dim3(Sn / 64, Hn, Bn), 256, FLASH_SMEM_BYTES>>>(gq, gk, gv, go);

    // ---- Output projection ----
    gemm64_kernel<<<g64h, 256>>>(go, Ao, mask, gh, Mn, NEn * Rn, HDn);
    gemm128_kernel<<<g128, 256>>>(go, Wo, bo, out, Mn, En, HDn, 0);
    gemm128_kernel<<<g128, 256>>>(gh, Bo, nullptr, out, Mn, En, NEn * Rn, 1);
}

// round 4
// speedup vs baseline: 1.0908x; 1.0908x over previous
#include <cuda_runtime.h>
#include <cstdint>

// Problem constants
#define Bn  2
#define Sn  2048
#define En  2048
#define Hn  16
#define Dn  128
#define NEn 8
#define Rn  16
#define HDn 2048
#define Mn  4096            // B*S
#define NEG_BIG -3.0e38f

// ---------------- scratch (device globals: no cudaMalloc allowed) ----------
__device__ float g_q[(size_t)Mn * HDn];
__device__ float g_k[(size_t)Mn * HDn];
__device__ float g_v[(size_t)Mn * HDn];
__device__ float g_o[(size_t)Mn * HDn];
__device__ float g_h[(size_t)Mn * (NEn * Rn)];

// ---------------------------------------------------------------------------
// tf32 helpers
// ---------------------------------------------------------------------------
__device__ __forceinline__ uint32_t f2tf(float x) {
    uint32_t r;
    asm("cvt.rna.tf32.f32 %0, %1;" : "=r"(r) : "f"(x));
    return r;
}

// hi/lo split: x ~= hi + lo, both representable in tf32
__device__ __forceinline__ void split_tf(float x, uint32_t& hi, uint32_t& lo) {
    hi = f2tf(x);
    lo = f2tf(x - __uint_as_float(hi));
}

__device__ __forceinline__ void mma8(float* c, const uint32_t* a, const uint32_t* b) {
    asm volatile(
        "mma.sync.aligned.m16n8k8.row.col.f32.tf32.tf32.f32 "
        "{%0,%1,%2,%3}, {%4,%5,%6,%7}, {%8,%9}, {%0,%1,%2,%3};\n"
        : "+f"(c[0]), "+f"(c[1]), "+f"(c[2]), "+f"(c[3])
        : "r"(a[0]), "r"(a[1]), "r"(a[2]), "r"(a[3]), "r"(b[0]), "r"(b[1]));
}

// ---------------------------------------------------------------------------
// tgemm3x: C[M,N] = A[M,K] @ B[N,K]^T  (3xTF32 split: hi*hi + hi*lo + lo*hi)
//   optional +bias[n], optional +=C (accFlag), optional *mask (h-GEMM, N=128)
// BM=BN=128, BK=16, 256 threads (8 warps of 32x64), mma m16n8k8
// ---------------------------------------------------------------------------
__global__ void __launch_bounds__(256) tgemm_kernel(
    const float* __restrict__ A, const float* __restrict__ Bm,
    const float* __restrict__ bias, const float* __restrict__ mask,
    float* __restrict__ C, int M, int N, int K, int accFlag)
{
    // [split][row][k]  split 0 = hi, 1 = lo
    __shared__ uint32_t As[2][128][20];
    __shared__ uint32_t Bs[2][128][20];
    const int bm = blockIdx.y * 128;
    const int bn = blockIdx.x * 128;
    const int tid  = threadIdx.x;
    const int lane = tid & 31;
    const int w    = tid >> 5;
    const int wm   = (w & 3) * 32;   // warp row offset within CTA tile
    const int wn   = (w >> 2) * 64;  // warp col offset
    const int grp  = lane >> 2;      // 0..7
    const int qt   = lane & 3;       // 0..3

    float acc[2][8][4];
#pragma unroll
    for (int mt = 0; mt < 2; mt++)
#pragma unroll
        for (int nt = 0; nt < 8; nt++)
#pragma unroll
            for (int e = 0; e < 4; e++) acc[mt][nt][e] = 0.f;

    const int lr = tid >> 2;         // 0..63
    const int lc = (tid & 3) * 4;    // 0,4,8,12
    const float* Ab = A  + (size_t)(bm + lr) * K + lc;
    const float* Bb = Bm + (size_t)(bn + lr) * K + lc;

    for (int k0 = 0; k0 < K; k0 += 16) {
        __syncthreads();
#pragma unroll
        for (int h = 0; h < 2; h++) {
            float4 a = *(const float4*)(Ab + (size_t)h * 64 * K + k0);
            uint4 ahi, alo;
            split_tf(a.x, ahi.x, alo.x);
            split_tf(a.y, ahi.y, alo.y);
            split_tf(a.z, ahi.z, alo.z);
            split_tf(a.w, ahi.w, alo.w);
            *(uint4*)&As[0][lr + h * 64][lc] = ahi;
            *(uint4*)&As[1][lr + h * 64][lc] = alo;
            float4 b = *(const float4*)(Bb + (size_t)h * 64 * K + k0);
            uint4 bhi, blo;
            split_tf(b.x, bhi.x, blo.x);
            split_tf(b.y, bhi.y, blo.y);
            split_tf(b.z, bhi.z, blo.z);
            split_tf(b.w, bhi.w, blo.w);
            *(uint4*)&Bs[0][lr + h * 64][lc] = bhi;
            *(uint4*)&Bs[1][lr + h * 64][lc] = blo;
        }
        __syncthreads();
#pragma unroll
        for (int kk = 0; kk < 16; kk += 8) {
            uint32_t af[2][2][4];   // [split][mt][frag]
#pragma unroll
            for (int sp = 0; sp < 2; sp++) {
#pragma unroll
                for (int mt = 0; mt < 2; mt++) {
                    int r = wm + mt * 16 + grp;
                    af[sp][mt][0] = As[sp][r][kk + qt];
                    af[sp][mt][1] = As[sp][r + 8][kk + qt];
                    af[sp][mt][2] = As[sp][r][kk + qt + 4];
                    af[sp][mt][3] = As[sp][r + 8][kk + qt + 4];
                }
            }
#pragma unroll
            for (int nt = 0; nt < 8; nt++) {
                int n = wn + nt * 8 + grp;
                uint32_t bhi[2], blo[2];
                bhi[0] = Bs[0][n][kk + qt];
                bhi[1] = Bs[0][n][kk + qt + 4];
                blo[0] = Bs[1][n][kk + qt];
                blo[1] = Bs[1][n][kk + qt + 4];
#pragma unroll
                for (int mt = 0; mt < 2; mt++) {
                    // small terms first, then hi*hi
                    mma8(acc[mt][nt], af[0][mt], blo);   // hi * lo
                    mma8(acc[mt][nt], af[1][mt], bhi);   // lo * hi
                    mma8(acc[mt][nt], af[0][mt], bhi);   // hi * hi
                }
            }
        }
    }

    // epilogue
#pragma unroll
    for (int mt = 0; mt < 2; mt++) {
#pragma unroll
        for (int nt = 0; nt < 8; nt++) {
            int m0 = bm + wm + mt * 16 + grp;
            int n  = bn + wn + nt * 8 + qt * 2;
            float c0 = acc[mt][nt][0], c1 = acc[mt][nt][1];
            float c2 = acc[mt][nt][2], c3 = acc[mt][nt][3];
            if (bias) {
                float b0 = bias[n], b1 = bias[n + 1];
                c0 += b0; c1 += b1; c2 += b0; c3 += b1;
            }
            if (mask) {   // h-GEMM: N=128, expert = n>>4 (R=16 contiguous)
                float s0 = mask[(size_t)m0 * NEn + (n >> 4)];
                float s1 = mask[(size_t)(m0 + 8) * NEn + (n >> 4)];
                c0 *= s0; c1 *= s0; c2 *= s1; c3 *= s1;
            }
            float* p0 = &C[(size_t)m0 * N + n];
            float* p1 = &C[(size_t)(m0 + 8) * N + n];
            if (accFlag) {
                float2 o0 = *(float2*)p0;
                float2 o1 = *(float2*)p1;
                c0 += o0.x; c1 += o0.y; c2 += o1.x; c3 += o1.y;
            }
            *(float2*)p0 = make_float2(c0, c1);
            *(float2*)p1 = make_float2(c2, c3);
        }
    }
}

// ---------------------------------------------------------------------------
// RoPE (in-place on q and k).  layout [B,S,H,D]; pair (i, i+64)
// ---------------------------------------------------------------------------
__global__ void rope_kernel(float* __restrict__ q, float* __restrict__ k)
{
    const int total = Bn * Sn * Hn * (Dn / 2);
    int idx = blockIdx.x * blockDim.x + threadIdx.x;
    if (idx >= total) return;
    int i = idx & 63;
    int s = (idx >> 10) & (Sn - 1);
    float inv = (float)exp(-(double)i * 0.14391156831212788);  // ln(10000)/64
    float ang = (float)s * inv;
    float c, sn;
    sincosf(ang, &sn, &c);
    size_t base = ((size_t)(idx >> 6)) * 128;
    float q0 = q[base + i], q1 = q[base + i + 64];
    q[base + i]      = q0 * c - q1 * sn;
    q[base + i + 64] = q1 * c + q0 * sn;
    float k0 = k[base + i], k1 = k[base + i + 64];
    k[base + i]      = k0 * c - k1 * sn;
    k[base + i + 64] = k1 * c + k0 * sn;
}

// ---------------------------------------------------------------------------
// Flash attention, fp32. grid (S/64, H, B), 256 threads.
// ---------------------------------------------------------------------------
#define FLASH_SMEM_FLOATS (2 * 128 * 68 + 64 * 132 + 64 * 68 + 3 * 64)
#define FLASH_SMEM_BYTES  (FLASH_SMEM_FLOATS * 4)

__global__ void __launch_bounds__(256) flash_kernel(
    const float* __restrict__ Q, const float* __restrict__ K,
    const float* __restrict__ V, float* __restrict__ O)
{
    extern __shared__ float sm[];
    float (*Qs)[68]  = (float(*)[68])sm;
    float (*Ks)[68]  = (float(*)[68])(sm + 128 * 68);
    float (*Vs)[132] = (float(*)[132])(sm + 2 * 128 * 68);
    float (*Ps)[68]  = (float(*)[68])(sm + 2 * 128 * 68 + 64 * 132);
    float* m_s    = sm + 2 * 128 * 68 + 64 * 132 + 64 * 68;
    float* l_s    = m_s + 64;
    float* corr_s = l_s + 64;

    const int q0 = blockIdx.x * 64;
    const int h  = blockIdx.y;
    const int b  = blockIdx.z;
    const int tid = threadIdx.x;
    const int tx = tid & 15, ty = tid >> 4;
    const int r4 = tid >> 2;
    const int c4 = tid & 3;

    const float scale = 0.08838834764831845f;

    {
        const float4* src = (const float4*)(Q + ((((size_t)b * Sn + q0 + r4) * Hn + h) << 7));
#pragma unroll
        for (int f = 0; f < 8; f++) {
            int fi = c4 * 8 + f;
            float4 v = src[fi];
            int d = fi * 4;
            Qs[d + 0][r4] = v.x * scale;
            Qs[d + 1][r4] = v.y * scale;
            Qs[d + 2][r4] = v.z * scale;
            Qs[d + 3][r4] = v.w * scale;
        }
    }
    if (tid < 64) { m_s[tid] = NEG_BIG; l_s[tid] = 0.f; }

    float4 oa[8];
#pragma unroll
    for (int f = 0; f < 8; f++) oa[f] = make_float4(0.f, 0.f, 0.f, 0.f);

    for (int j0 = 0; j0 <= q0; j0 += 64) {
        __syncthreads();
        {
            const float* kb = K + ((((size_t)b * Sn + j0 + r4) * Hn + h) << 7);
            const float* vb = V + ((((size_t)b * Sn + j0 + r4) * Hn + h) << 7);
            const float4* ks = (const float4*)kb;
            const float4* vs = (const float4*)vb;
            float4* vrow = (float4*)&Vs[r4][0];
#pragma unroll
            for (int f = 0; f < 8; f++) {
                int fi = c4 * 8 + f;
                float4 kv = ks[fi];
                int d = fi * 4;
                Ks[d + 0][r4] = kv.x;
                Ks[d + 1][r4] = kv.y;
                Ks[d + 2][r4] = kv.z;
                Ks[d + 3][r4] = kv.w;
                vrow[fi] = vs[fi];
            }
        }
        __syncthreads();

        float s[4][4];
#pragma unroll
        for (int i = 0; i < 4; i++)
#pragma unroll
            for (int j = 0; j < 4; j++) s[i][j] = 0.f;

        for (int d = 0; d < 128; d++) {
            float4 qv = *(const float4*)&Qs[d][ty * 4];
            float4 kv = *(const float4*)&Ks[d][tx * 4];
            float qa[4] = {qv.x, qv.y, qv.z, qv.w};
            float ka[4] = {kv.x, kv.y, kv.z, kv.w};
#pragma unroll
            for (int i = 0; i < 4; i++)
#pragma unroll
                for (int j = 0; j < 4; j++)
                    s[i][j] = fmaf(qa[i], ka[j], s[i][j]);
        }

        if (j0 == q0) {
#pragma unroll
            for (int i = 0; i < 4; i++)
#pragma unroll
                for (int j = 0; j < 4; j++)
                    if (ty * 4 + i < tx * 4 + j) s[i][j] = NEG_BIG;
        }

#pragma unroll
        for (int i = 0; i < 4; i++) {
            float rm = fmaxf(fmaxf(s[i][0], s[i][1]), fmaxf(s[i][2], s[i][3]));
#pragma unroll
            for (int off = 8; off > 0; off >>= 1)
                rm = fmaxf(rm, __shfl_xor_sync(0xffffffffu, rm, off));
            if (tx == 0) {
                int row = ty * 4 + i;
                float mo = m_s[row];
                float mn = fmaxf(mo, rm);
                m_s[row] = mn;
                corr_s[row] = __expf(mo - mn);
            }
        }
        __syncthreads();

#pragma unroll
        for (int i = 0; i < 4; i++) {
            int row = ty * 4 + i;
            float mn = m_s[row];
            float rs = 0.f;
#pragma unroll
            for (int j = 0; j < 4; j++) {
                float p = __expf(s[i][j] - mn);
                Ps[row][tx * 4 + j] = p;
                rs += p;
            }
#pragma unroll
            for (int off = 8; off > 0; off >>= 1)
                rs += __shfl_xor_sync(0xffffffffu, rs, off);
            if (tx == 0) l_s[row] = l_s[row] * corr_s[row] + rs;
        }
        __syncthreads();

        {
            float cr = corr_s[r4];
#pragma unroll
            for (int f = 0; f < 8; f++) {
                oa[f].x *= cr; oa[f].y *= cr; oa[f].z *= cr; oa[f].w *= cr;
            }
            for (int j = 0; j < 64; j++) {
                float p = Ps[r4][j];
                const float4* vrow = (const float4*)&Vs[j][0];
#pragma unroll
                for (int f = 0; f < 8; f++) {
                    float4 v = vrow[c4 + 4 * f];
                    oa[f].x = fmaf(p, v.x, oa[f].x);
                    oa[f].y = fmaf(p, v.y, oa[f].y);
                    oa[f].z = fmaf(p, v.z, oa[f].z);
                    oa[f].w = fmaf(p, v.w, oa[f].w);
                }
            }
        }
    }

    {
        float invl = 1.f / l_s[r4];
        float4* dst = (float4*)(O + ((((size_t)b * Sn + q0 + r4) * Hn + h) << 7));
#pragma unroll
        for (int f = 0; f < 8; f++) {
            float4 v = oa[f];
            v.x *= invl; v.y *= invl; v.z *= invl; v.w *= invl;
            dst[c4 + 4 * f] = v;
        }
    }
}

// ---------------------------------------------------------------------------
extern "C" void kernel_launch(void* const* d_in, const int* in_sizes, int n_in,
                              void* d_out, int out_size)
{
    const float* x    = (const float*)d_in[0];
    const float* mask = (const float*)d_in[1];
    const float* Wq = (const float*)d_in[2];
    const float* bq = (const float*)d_in[3];
    const float* Aq = (const float*)d_in[4];
    const float* Bq = (const float*)d_in[5];
    const float* Wk = (const float*)d_in[6];
    const float* bk = (const float*)d_in[7];
    const float* Ak = (const float*)d_in[8];
    const float* Bk = (const float*)d_in[9];
    const float* Wv = (const float*)d_in[10];
    const float* bv = (const float*)d_in[11];
    const float* Av = (const float*)d_in[12];
    const float* Bv = (const float*)d_in[13];
    const float* Wo = (const float*)d_in[14];
    const float* bo = (const float*)d_in[15];
    const float* Ao = (const float*)d_in[16];
    const float* Bo = (const float*)d_in[17];
    float* out = (float*)d_out;

    float *gq, *gk, *gv, *go, *gh;
    cudaGetSymbolAddress((void**)&gq, g_q);
    cudaGetSymbolAddress((void**)&gk, g_k);
    cudaGetSymbolAddress((void**)&gv, g_v);
    cudaGetSymbolAddress((void**)&go, g_o);
    cudaGetSymbolAddress((void**)&gh, g_h);

    dim3 gD(HDn / 128, Mn / 128);           // dense: (16, 32)
    dim3 gH((NEn * Rn) / 128, Mn / 128);    // low-rank h: (1, 32)

    // ---- Q ----
    tgemm_kernel<<<gH, 256>>>(x, Aq, nullptr, mask, gh, Mn, NEn * Rn, En, 0);
    tgemm_kernel<<<gD, 256>>>(x, Wq, bq, nullptr, gq, Mn, HDn, En, 0);
    tgemm_kernel<<<gD, 256>>>(gh, Bq, nullptr, nullptr, gq, Mn, HDn, NEn * Rn, 1);
    // ---- K ----
    tgemm_kernel<<<gH, 256>>>(x, Ak, nullptr, mask, gh, Mn, NEn * Rn, En, 0);
    tgemm_kernel<<<gD, 256>>>(x, Wk, bk, nullptr, gk, Mn, HDn, En, 0);
    tgemm_kernel<<<gD, 256>>>(gh, Bk, nullptr, nullptr, gk, Mn, HDn, NEn * Rn, 1);
    // ---- V ----
    tgemm_kernel<<<gH, 256>>>(x, Av, nullptr, mask, gh, Mn, NEn * Rn, En, 0);
    tgemm_kernel<<<gD, 256>>>(x, Wv, bv, nullptr, gv, Mn, HDn, En, 0);
    tgemm_kernel<<<gD, 256>>>(gh, Bv, nullptr, nullptr, gv, Mn, HDn, NEn * Rn, 1);

    // ---- RoPE ----
    {
        int total = Bn * Sn * Hn * (Dn / 2);
        rope_kernel<<<(total + 255) / 256, 256>>>(gq, gk);
    }

    // ---- Attention ----
    cudaFuncSetAttribute(flash_kernel, cudaFuncAttributeMaxDynamicSharedMemorySize,
                         FLASH_SMEM_BYTES);
    flash_kernel<<<dim3(Sn / 64, Hn, Bn), 256, FLASH_SMEM_BYTES>>>(gq, gk, gv, go);

    // ---- Output projection ----
    tgemm_kernel<<<gH, 256>>>(go, Ao, nullptr, mask, gh, Mn, NEn * Rn, HDn, 0);
    tgemm_kernel<<<gD, 256>>>(go, Wo, bo, nullptr, out, Mn, En, HDn, 0);
    tgemm_kernel<<<gD, 256>>>(gh, Bo, nullptr, nullptr, out, Mn, En, NEn * Rn, 1);
}

// round 5
// speedup vs baseline: 1.0913x; 1.0005x over previous
#include <cuda_runtime.h>
#include <cstdint>

// Problem constants
#define Bn  2
#define Sn  2048
#define En  2048
#define Hn  16
#define Dn  128
#define NEn 8
#define Rn  16
#define HDn 2048
#define Mn  4096            // B*S
#define NEG_BIG -3.0e38f

// ---------------- scratch (device globals: no cudaMalloc allowed) ----------
__device__ float g_q[(size_t)Mn * HDn];
__device__ float g_k[(size_t)Mn * HDn];
__device__ float g_v[(size_t)Mn * HDn];
__device__ float g_o[(size_t)Mn * HDn];
__device__ float g_h[(size_t)Mn * (NEn * Rn)];

// ---------------------------------------------------------------------------
// tf32 helpers
// ---------------------------------------------------------------------------
__device__ __forceinline__ uint32_t f2tf(float x) {
    uint32_t r;
    asm("cvt.rna.tf32.f32 %0, %1;" : "=r"(r) : "f"(x));
    return r;
}

// hi/lo split: x ~= hi + lo, both representable in tf32
__device__ __forceinline__ void split_tf(float x, uint32_t& hi, uint32_t& lo) {
    hi = f2tf(x);
    lo = f2tf(x - __uint_as_float(hi));
}

__device__ __forceinline__ void mma8(float* c, const uint32_t* a, const uint32_t* b) {
    asm volatile(
        "mma.sync.aligned.m16n8k8.row.col.f32.tf32.tf32.f32 "
        "{%0,%1,%2,%3}, {%4,%5,%6,%7}, {%8,%9}, {%0,%1,%2,%3};\n"
        : "+f"(c[0]), "+f"(c[1]), "+f"(c[2]), "+f"(c[3])
        : "r"(a[0]), "r"(a[1]), "r"(a[2]), "r"(a[3]), "r"(b[0]), "r"(b[1]));
}

// ---------------------------------------------------------------------------
// tgemm3x: C[M,N] = A[M,K] @ B[N,K]^T  (3xTF32 split: hi*hi + hi*lo + lo*hi)
//   optional +bias[n], optional +=C (accFlag), optional *mask (h-GEMM, N=128)
// BM=BN=128, BK=16, 256 threads (8 warps of 32x64), mma m16n8k8
// ---------------------------------------------------------------------------
__global__ void __launch_bounds__(256) tgemm_kernel(
    const float* __restrict__ A, const float* __restrict__ Bm,
    const float* __restrict__ bias, const float* __restrict__ mask,
    float* __restrict__ C, int M, int N, int K, int accFlag)
{
    // [split][row][k]  split 0 = hi, 1 = lo
    __shared__ uint32_t As[2][128][20];
    __shared__ uint32_t Bs[2][128][20];
    const int bm = blockIdx.y * 128;
    const int bn = blockIdx.x * 128;
    const int tid  = threadIdx.x;
    const int lane = tid & 31;
    const int w    = tid >> 5;
    const int wm   = (w & 3) * 32;   // warp row offset within CTA tile
    const int wn   = (w >> 2) * 64;  // warp col offset
    const int grp  = lane >> 2;      // 0..7
    const int qt   = lane & 3;       // 0..3

    float acc[2][8][4];
#pragma unroll
    for (int mt = 0; mt < 2; mt++)
#pragma unroll
        for (int nt = 0; nt < 8; nt++)
#pragma unroll
            for (int e = 0; e < 4; e++) acc[mt][nt][e] = 0.f;

    const int lr = tid >> 2;         // 0..63
    const int lc = (tid & 3) * 4;    // 0,4,8,12
    const float* Ab = A  + (size_t)(bm + lr) * K + lc;
    const float* Bb = Bm + (size_t)(bn + lr) * K + lc;

    for (int k0 = 0; k0 < K; k0 += 16) {
        __syncthreads();
#pragma unroll
        for (int h = 0; h < 2; h++) {
            float4 a = *(const float4*)(Ab + (size_t)h * 64 * K + k0);
            uint4 ahi, alo;
            split_tf(a.x, ahi.x, alo.x);
            split_tf(a.y, ahi.y, alo.y);
            split_tf(a.z, ahi.z, alo.z);
            split_tf(a.w, ahi.w, alo.w);
            *(uint4*)&As[0][lr + h * 64][lc] = ahi;
            *(uint4*)&As[1][lr + h * 64][lc] = alo;
            float4 b = *(const float4*)(Bb + (size_t)h * 64 * K + k0);
            uint4 bhi, blo;
            split_tf(b.x, bhi.x, blo.x);
            split_tf(b.y, bhi.y, blo.y);
            split_tf(b.z, bhi.z, blo.z);
            split_tf(b.w, bhi.w, blo.w);
            *(uint4*)&Bs[0][lr + h * 64][lc] = bhi;
            *(uint4*)&Bs[1][lr + h * 64][lc] = blo;
        }
        __syncthreads();
#pragma unroll
        for (int kk = 0; kk < 16; kk += 8) {
            uint32_t af[2][2][4];   // [split][mt][frag]
#pragma unroll
            for (int sp = 0; sp < 2; sp++) {
#pragma unroll
                for (int mt = 0; mt < 2; mt++) {
                    int r = wm + mt * 16 + grp;
                    af[sp][mt][0] = As[sp][r][kk + qt];
                    af[sp][mt][1] = As[sp][r + 8][kk + qt];
                    af[sp][mt][2] = As[sp][r][kk + qt + 4];
                    af[sp][mt][3] = As[sp][r + 8][kk + qt + 4];
                }
            }
#pragma unroll
            for (int nt = 0; nt < 8; nt++) {
                int n = wn + nt * 8 + grp;
                uint32_t bhi[2], blo[2];
                bhi[0] = Bs[0][n][kk + qt];
                bhi[1] = Bs[0][n][kk + qt + 4];
                blo[0] = Bs[1][n][kk + qt];
                blo[1] = Bs[1][n][kk + qt + 4];
#pragma unroll
                for (int mt = 0; mt < 2; mt++) {
                    // small terms first, then hi*hi
                    mma8(acc[mt][nt], af[0][mt], blo);   // hi * lo
                    mma8(acc[mt][nt], af[1][mt], bhi);   // lo * hi
                    mma8(acc[mt][nt], af[0][mt], bhi);   // hi * hi
                }
            }
        }
    }

    // epilogue
#pragma unroll
    for (int mt = 0; mt < 2; mt++) {
#pragma unroll
        for (int nt = 0; nt < 8; nt++) {
            int m0 = bm + wm + mt * 16 + grp;
            int n  = bn + wn + nt * 8 + qt * 2;
            float c0 = acc[mt][nt][0], c1 = acc[mt][nt][1];
            float c2 = acc[mt][nt][2], c3 = acc[mt][nt][3];
            if (bias) {
                float b0 = bias[n], b1 = bias[n + 1];
                c0 += b0; c1 += b1; c2 += b0; c3 += b1;
            }
            if (mask) {   // h-GEMM: N=128, expert = n>>4 (R=16 contiguous)
                float s0 = mask[(size_t)m0 * NEn + (n >> 4)];
                float s1 = mask[(size_t)(m0 + 8) * NEn + (n >> 4)];
                c0 *= s0; c1 *= s0; c2 *= s1; c3 *= s1;
            }
            float* p0 = &C[(size_t)m0 * N + n];
            float* p1 = &C[(size_t)(m0 + 8) * N + n];
            if (accFlag) {
                float2 o0 = *(float2*)p0;
                float2 o1 = *(float2*)p1;
                c0 += o0.x; c1 += o0.y; c2 += o1.x; c3 += o1.y;
            }
            *(float2*)p0 = make_float2(c0, c1);
            *(float2*)p1 = make_float2(c2, c3);
        }
    }
}

// ---------------------------------------------------------------------------
// RoPE (in-place on q and k).  layout [B,S,H,D]; pair (i, i+64)
// ---------------------------------------------------------------------------
__global__ void rope_kernel(float* __restrict__ q, float* __restrict__ k)
{
    const int total = Bn * Sn * Hn * (Dn / 2);
    int idx = blockIdx.x * blockDim.x + threadIdx.x;
    if (idx >= total) return;
    int i = idx & 63;
    int s = (idx >> 10) & (Sn - 1);
    float inv = (float)exp(-(double)i * 0.14391156831212788);  // ln(10000)/64
    float ang = (float)s * inv;
    float c, sn;
    sincosf(ang, &sn, &c);
    size_t base = ((size_t)(idx >> 6)) * 128;
    float q0 = q[base + i], q1 = q[base + i + 64];
    q[base + i]      = q0 * c - q1 * sn;
    q[base + i + 64] = q1 * c + q0 * sn;
    float k0 = k[base + i], k1 = k[base + i + 64];
    k[base + i]      = k0 * c - k1 * sn;
    k[base + i + 64] = k1 * c + k0 * sn;
}

// ---------------------------------------------------------------------------
// Flash attention, fp32. grid (S/64, H, B), 256 threads.
// ---------------------------------------------------------------------------
#define FLASH_SMEM_FLOATS (2 * 128 * 68 + 64 * 132 + 64 * 68 + 3 * 64)
#define FLASH_SMEM_BYTES  (FLASH_SMEM_FLOATS * 4)

__global__ void __launch_bounds__(256) flash_kernel(
    const float* __restrict__ Q, const float* __restrict__ K,
    const float* __restrict__ V, float* __restrict__ O)
{
    extern __shared__ float sm[];
    float (*Qs)[68]  = (float(*)[68])sm;
    float (*Ks)[68]  = (float(*)[68])(sm + 128 * 68);
    float (*Vs)[132] = (float(*)[132])(sm + 2 * 128 * 68);
    float (*Ps)[68]  = (float(*)[68])(sm + 2 * 128 * 68 + 64 * 132);
    float* m_s    = sm + 2 * 128 * 68 + 64 * 132 + 64 * 68;
    float* l_s    = m_s + 64;
    float* corr_s = l_s + 64;

    const int q0 = blockIdx.x * 64;
    const int h  = blockIdx.y;
    const int b  = blockIdx.z;
    const int tid = threadIdx.x;
    const int tx = tid & 15, ty = tid >> 4;
    const int r4 = tid >> 2;
    const int c4 = tid & 3;

    const float scale = 0.08838834764831845f;

    {
        const float4* src = (const float4*)(Q + ((((size_t)b * Sn + q0 + r4) * Hn + h) << 7));
#pragma unroll
        for (int f = 0; f < 8; f++) {
            int fi = c4 * 8 + f;
            float4 v = src[fi];
            int d = fi * 4;
            Qs[d + 0][r4] = v.x * scale;
            Qs[d + 1][r4] = v.y * scale;
            Qs[d + 2][r4] = v.z * scale;
            Qs[d + 3][r4] = v.w * scale;
        }
    }
    if (tid < 64) { m_s[tid] = NEG_BIG; l_s[tid] = 0.f; }

    float4 oa[8];
#pragma unroll
    for (int f = 0; f < 8; f++) oa[f] = make_float4(0.f, 0.f, 0.f, 0.f);

    for (int j0 = 0; j0 <= q0; j0 += 64) {
        __syncthreads();
        {
            const float* kb = K + ((((size_t)b * Sn + j0 + r4) * Hn + h) << 7);
            const float* vb = V + ((((size_t)b * Sn + j0 + r4) * Hn + h) << 7);
            const float4* ks = (const float4*)kb;
            const float4* vs = (const float4*)vb;
            float4* vrow = (float4*)&Vs[r4][0];
#pragma unroll
            for (int f = 0; f < 8; f++) {
                int fi = c4 * 8 + f;
                float4 kv = ks[fi];
                int d = fi * 4;
                Ks[d + 0][r4] = kv.x;
                Ks[d + 1][r4] = kv.y;
                Ks[d + 2][r4] = kv.z;
                Ks[d + 3][r4] = kv.w;
                vrow[fi] = vs[fi];
            }
        }
        __syncthreads();

        float s[4][4];
#pragma unroll
        for (int i = 0; i < 4; i++)
#pragma unroll
            for (int j = 0; j < 4; j++) s[i][j] = 0.f;

        for (int d = 0; d < 128; d++) {
            float4 qv = *(const float4*)&Qs[d][ty * 4];
            float4 kv = *(const float4*)&Ks[d][tx * 4];
            float qa[4] = {qv.x, qv.y, qv.z, qv.w};
            float ka[4] = {kv.x, kv.y, kv.z, kv.w};
#pragma unroll
            for (int i = 0; i < 4; i++)
#pragma unroll
                for (int j = 0; j < 4; j++)
                    s[i][j] = fmaf(qa[i], ka[j], s[i][j]);
        }

        if (j0 == q0) {
#pragma unroll
            for (int i = 0; i < 4; i++)
#pragma unroll
                for (int j = 0; j < 4; j++)
                    if (ty * 4 + i < tx * 4 + j) s[i][j] = NEG_BIG;
        }

#pragma unroll
        for (int i = 0; i < 4; i++) {
            float rm = fmaxf(fmaxf(s[i][0], s[i][1]), fmaxf(s[i][2], s[i][3]));
#pragma unroll
            for (int off = 8; off > 0; off >>= 1)
                rm = fmaxf(rm, __shfl_xor_sync(0xffffffffu, rm, off));
            if (tx == 0) {
                int row = ty * 4 + i;
                float mo = m_s[row];
                float mn = fmaxf(mo, rm);
                m_s[row] = mn;
                corr_s[row] = __expf(mo - mn);
            }
        }
        __syncthreads();

#pragma unroll
        for (int i = 0; i < 4; i++) {
            int row = ty * 4 + i;
            float mn = m_s[row];
            float rs = 0.f;
#pragma unroll
            for (int j = 0; j < 4; j++) {
                float p = __expf(s[i][j] - mn);
                Ps[row][tx * 4 + j] = p;
                rs += p;
            }
#pragma unroll
            for (int off = 8; off > 0; off >>= 1)
                rs += __shfl_xor_sync(0xffffffffu, rs, off);
            if (tx == 0) l_s[row] = l_s[row] * corr_s[row] + rs;
        }
        __syncthreads();

        {
            float cr = corr_s[r4];
#pragma unroll
            for (int f = 0; f < 8; f++) {
                oa[f].x *= cr; oa[f].y *= cr; oa[f].z *= cr; oa[f].w *= cr;
            }
            for (int j = 0; j < 64; j++) {
                float p = Ps[r4][j];
                const float4* vrow = (const float4*)&Vs[j][0];
#pragma unroll
                for (int f = 0; f < 8; f++) {
                    float4 v = vrow[c4 + 4 * f];
                    oa[f].x = fmaf(p, v.x, oa[f].x);
                    oa[f].y = fmaf(p, v.y, oa[f].y);
                    oa[f].z = fmaf(p, v.z, oa[f].z);
                    oa[f].w = fmaf(p, v.w, oa[f].w);
                }
            }
        }
    }

    {
        float invl = 1.f / l_s[r4];
        float4* dst = (float4*)(O + ((((size_t)b * Sn + q0 + r4) * Hn + h) << 7));
#pragma unroll
        for (int f = 0; f < 8; f++) {
            float4 v = oa[f];
            v.x *= invl; v.y *= invl; v.z *= invl; v.w *= invl;
            dst[c4 + 4 * f] = v;
        }
    }
}

// ---------------------------------------------------------------------------
extern "C" void kernel_launch(void* const* d_in, const int* in_sizes, int n_in,
                              void* d_out, int out_size)
{
    const float* x    = (const float*)d_in[0];
    const float* mask = (const float*)d_in[1];
    const float* Wq = (const float*)d_in[2];
    const float* bq = (const float*)d_in[3];
    const float* Aq = (const float*)d_in[4];
    const float* Bq = (const float*)d_in[5];
    const float* Wk = (const float*)d_in[6];
    const float* bk = (const float*)d_in[7];
    const float* Ak = (const float*)d_in[8];
    const float* Bk = (const float*)d_in[9];
    const float* Wv = (const float*)d_in[10];
    const float* bv = (const float*)d_in[11];
    const float* Av = (const float*)d_in[12];
    const float* Bv = (const float*)d_in[13];
    const float* Wo = (const float*)d_in[14];
    const float* bo = (const float*)d_in[15];
    const float* Ao = (const float*)d_in[16];
    const float* Bo = (const float*)d_in[17];
    float* out = (float*)d_out;

    float *gq, *gk, *gv, *go, *gh;
    cudaGetSymbolAddress((void**)&gq, g_q);
    cudaGetSymbolAddress((void**)&gk, g_k);
    cudaGetSymbolAddress((void**)&gv, g_v);
    cudaGetSymbolAddress((void**)&go, g_o);
    cudaGetSymbolAddress((void**)&gh, g_h);

    dim3 gD(HDn / 128, Mn / 128);           // dense: (16, 32)
    dim3 gH((NEn * Rn) / 128, Mn / 128);    // low-rank h: (1, 32)

    // ---- Q ----
    tgemm_kernel<<<gH, 256>>>(x, Aq, nullptr, mask, gh, Mn, NEn * Rn, En, 0);
    tgemm_kernel<<<gD, 256>>>(x, Wq, bq, nullptr, gq, Mn, HDn, En, 0);
    tgemm_kernel<<<gD, 256>>>(gh, Bq, nullptr, nullptr, gq, Mn, HDn, NEn * Rn, 1);
    // ---- K ----
    tgemm_kernel<<<gH, 256>>>(x, Ak, nullptr, mask, gh, Mn, NEn * Rn, En, 0);
    tgemm_kernel<<<gD, 256>>>(x, Wk, bk, nullptr, gk, Mn, HDn, En, 0);
    tgemm_kernel<<<gD, 256>>>(gh, Bk, nullptr, nullptr, gk, Mn, HDn, NEn * Rn, 1);
    // ---- V ----
    tgemm_kernel<<<gH, 256>>>(x, Av, nullptr, mask, gh, Mn, NEn * Rn, En, 0);
    tgemm_kernel<<<gD, 256>>>(x, Wv, bv, nullptr, gv, Mn, HDn, En, 0);
    tgemm_kernel<<<gD, 256>>>(gh, Bv, nullptr, nullptr, gv, Mn, HDn, NEn * Rn, 1);

    // ---- RoPE ----
    {
        int total = Bn * Sn * Hn * (Dn / 2);
        rope_kernel<<<(total + 255) / 256, 256>>>(gq, gk);
    }

    // ---- Attention ----
    cudaFuncSetAttribute(flash_kernel, cudaFuncAttributeMaxDynamicSharedMemorySize,
                         FLASH_SMEM_BYTES);
    flash_kernel<<<dim3(Sn / 64, Hn, Bn), 256, FLASH_SMEM_BYTES>>>(gq, gk, gv, go);

    // ---- Output projection ----
    tgemm_kernel<<<gH, 256>>>(go, Ao, nullptr, mask, gh, Mn, NEn * Rn, HDn, 0);
    tgemm_kernel<<<gD, 256>>>(go, Wo, bo, nullptr, out, Mn, En, HDn, 0);
    tgemm_kernel<<<gD, 256>>>(gh, Bo, nullptr, nullptr, out, Mn, En, NEn * Rn, 1);
}

// round 6
// speedup vs baseline: 1.5746x; 1.4429x over previous
#include <cuda_runtime.h>
#include <cuda_bf16.h>
#include <cstdint>

// Problem constants
#define Bn  2
#define Sn  2048
#define En  2048
#define Hn  16
#define Dn  128
#define NEn 8
#define Rn  16
#define HDn 2048
#define Mn  4096            // B*S
#define NEG_BIG -3.0e38f

// ---------------- scratch (device globals: no cudaMalloc allowed) ----------
__device__ float g_q[(size_t)Mn * HDn];
__device__ float g_k[(size_t)Mn * HDn];
__device__ float g_v[(size_t)Mn * HDn];
__device__ float g_o[(size_t)Mn * HDn];
__device__ float g_h[(size_t)Mn * (NEn * Rn)];

// ---------------------------------------------------------------------------
// mma / ldmatrix helpers
// ---------------------------------------------------------------------------
__device__ __forceinline__ void mma16(float* c, const uint32_t* a, const uint32_t* b) {
    asm volatile(
        "mma.sync.aligned.m16n8k16.row.col.f32.bf16.bf16.f32 "
        "{%0,%1,%2,%3}, {%4,%5,%6,%7}, {%8,%9}, {%0,%1,%2,%3};\n"
        : "+f"(c[0]), "+f"(c[1]), "+f"(c[2]), "+f"(c[3])
        : "r"(a[0]), "r"(a[1]), "r"(a[2]), "r"(a[3]), "r"(b[0]), "r"(b[1]));
}

__device__ __forceinline__ void ldsm4(uint32_t* r, uint32_t addr) {
    asm volatile(
        "ldmatrix.sync.aligned.m8n8.x4.shared.b16 {%0,%1,%2,%3}, [%4];"
        : "=r"(r[0]), "=r"(r[1]), "=r"(r[2]), "=r"(r[3]) : "r"(addr));
}

// convert float4 -> 4 bf16 hi + 4 bf16 lo, store 8B each
__device__ __forceinline__ void cvt_store(__nv_bfloat16* hp, __nv_bfloat16* lp, float4 v) {
    __nv_bfloat162 h01 = __floats2bfloat162_rn(v.x, v.y);
    __nv_bfloat162 h23 = __floats2bfloat162_rn(v.z, v.w);
    float lx = v.x - __bfloat162float(h01.x);
    float ly = v.y - __bfloat162float(h01.y);
    float lz = v.z - __bfloat162float(h23.x);
    float lw = v.w - __bfloat162float(h23.y);
    __nv_bfloat162 l01 = __floats2bfloat162_rn(lx, ly);
    __nv_bfloat162 l23 = __floats2bfloat162_rn(lz, lw);
    uint2 hu, lu;
    hu.x = *(uint32_t*)&h01; hu.y = *(uint32_t*)&h23;
    lu.x = *(uint32_t*)&l01; lu.y = *(uint32_t*)&l23;
    *(uint2*)hp = hu;
    *(uint2*)lp = lu;
}

// ---------------------------------------------------------------------------
// tgemm (bf16x3): C[M,N] = A[M,K] @ B[N,K]^T, fp32-accurate via hi/lo split.
//   optional +bias[n], optional *mask (expert gating), optional +=C.
// Template: BM x BN CTA tile, warp tile (MT*16) x (NT*8), NW warps.
// BK = 32, double-buffered smem, ldmatrix fragment loads.
// ---------------------------------------------------------------------------
template<int BM, int BN, int MT, int NT, int NW>
__global__ void __launch_bounds__(NW * 32) tgemm_kernel(
    const float* __restrict__ A, const float* __restrict__ Bm,
    const float* __restrict__ bias, const float* __restrict__ mask,
    float* __restrict__ C, int M, int N, int K, int accFlag)
{
    constexpr int NTHR = NW * 32;
    constexpr int LDW  = 40;                 // padded row width in bf16 (80B)
    constexpr int ASZ  = BM * LDW;           // bf16 elems per split
    constexpr int BSZ  = BN * LDW;
    constexpr int BUFSZ = 2 * (ASZ + BSZ);   // per buffer (hi+lo, A+B)
    constexpr int PFA  = BM * 8 / NTHR;      // float4 loads per thread (A)
    constexpr int PFB  = BN * 8 / NTHR;
    constexpr int WROWS = BM / (MT * 16);

    extern __shared__ __nv_bfloat16 sm[];
    const uint32_t smem_u32 = (uint32_t)__cvta_generic_to_shared(sm);

    const int bm = blockIdx.y * BM;
    const int bn = blockIdx.x * BN;
    const int tid  = threadIdx.x;
    const int lane = tid & 31;
    const int w    = tid >> 5;
    const int wm   = (w % WROWS) * (MT * 16);
    const int wn   = (w / WROWS) * (NT * 8);
    const int grp  = lane >> 2;
    const int qt   = lane & 3;

    // per-lane ldmatrix row/col offsets (constant across iterations)
    const int a_row = ((lane >> 3) & 1) * 8 + (lane & 7);
    const int a_col = (lane >> 4) * 8;
    const int b_row = (lane >> 4) * 8 + (lane & 7);
    const int b_col = ((lane >> 3) & 1) * 8;

    float acc[MT][NT][4];
#pragma unroll
    for (int mt = 0; mt < MT; mt++)
#pragma unroll
        for (int nt = 0; nt < NT; nt++)
#pragma unroll
            for (int e = 0; e < 4; e++) acc[mt][nt][e] = 0.f;

    float4 pfa[PFA], pfb[PFB];

    // global load of one 32-K tile into registers
    auto loadG = [&](int k0) {
#pragma unroll
        for (int i = 0; i < PFA; i++) {
            int idx = tid + i * NTHR;
            int row = idx >> 3, c = (idx & 7) * 4;
            pfa[i] = *(const float4*)(A + (size_t)(bm + row) * K + k0 + c);
        }
#pragma unroll
        for (int i = 0; i < PFB; i++) {
            int idx = tid + i * NTHR;
            int row = idx >> 3, c = (idx & 7) * 4;
            pfb[i] = *(const float4*)(Bm + (size_t)(bn + row) * K + k0 + c);
        }
    };
    // convert + store registers into smem buffer
    auto storeS = [&](int buf) {
        int base = buf * BUFSZ;
#pragma unroll
        for (int i = 0; i < PFA; i++) {
            int idx = tid + i * NTHR;
            int row = idx >> 3, c = (idx & 7) * 4;
            cvt_store(&sm[base + row * LDW + c],
                      &sm[base + ASZ + row * LDW + c], pfa[i]);
        }
#pragma unroll
        for (int i = 0; i < PFB; i++) {
            int idx = tid + i * NTHR;
            int row = idx >> 3, c = (idx & 7) * 4;
            cvt_store(&sm[base + 2 * ASZ + row * LDW + c],
                      &sm[base + 2 * ASZ + BSZ + row * LDW + c], pfb[i]);
        }
    };

    loadG(0);
    storeS(0);
    __syncthreads();

    const int nk = K >> 5;
    for (int it = 0; it < nk; it++) {
        const int buf = it & 1;
        if (it + 1 < nk) loadG((it + 1) << 5);

        const uint32_t aHi = smem_u32 + (uint32_t)(buf * BUFSZ) * 2;
        const uint32_t aLo = aHi + ASZ * 2;
        const uint32_t bHi = aHi + 2 * ASZ * 2;
        const uint32_t bLo = bHi + BSZ * 2;

#pragma unroll
        for (int kk = 0; kk < 32; kk += 16) {
            uint32_t afr[2][MT][4];
#pragma unroll
            for (int mt = 0; mt < MT; mt++) {
                uint32_t off = (uint32_t)((wm + mt * 16 + a_row) * LDW + kk + a_col) * 2;
                ldsm4(afr[0][mt], aHi + off);
                ldsm4(afr[1][mt], aLo + off);
            }
#pragma unroll
            for (int nb = 0; nb < NT / 2; nb++) {
                uint32_t off = (uint32_t)((wn + nb * 16 + b_row) * LDW + kk + b_col) * 2;
                uint32_t bh[4], bl[4];
                ldsm4(bh, bHi + off);
                ldsm4(bl, bLo + off);
#pragma unroll
                for (int hf = 0; hf < 2; hf++) {
#pragma unroll
                    for (int mt = 0; mt < MT; mt++) {
                        float* c = acc[mt][nb * 2 + hf];
                        mma16(c, afr[0][mt], &bl[hf * 2]);   // hi * lo
                        mma16(c, afr[1][mt], &bh[hf * 2]);   // lo * hi
                        mma16(c, afr[0][mt], &bh[hf * 2]);   // hi * hi
                    }
                }
            }
        }

        if (it + 1 < nk) storeS(buf ^ 1);
        __syncthreads();
    }

    // epilogue
#pragma unroll
    for (int mt = 0; mt < MT; mt++) {
#pragma unroll
        for (int nt = 0; nt < NT; nt++) {
            int m0 = bm + wm + mt * 16 + grp;
            int n  = bn + wn + nt * 8 + qt * 2;
            float c0 = acc[mt][nt][0], c1 = acc[mt][nt][1];
            float c2 = acc[mt][nt][2], c3 = acc[mt][nt][3];
            if (bias) {
                float b0 = bias[n], b1 = bias[n + 1];
                c0 += b0; c1 += b1; c2 += b0; c3 += b1;
            }
            if (mask) {   // h-GEMM: expert = n>>4 (R=16 contiguous)
                float s0 = mask[(size_t)m0 * NEn + (n >> 4)];
                float s1 = mask[(size_t)(m0 + 8) * NEn + (n >> 4)];
                c0 *= s0; c1 *= s0; c2 *= s1; c3 *= s1;
            }
            float* p0 = &C[(size_t)m0 * N + n];
            float* p1 = &C[(size_t)(m0 + 8) * N + n];
            if (accFlag) {
                float2 o0 = *(float2*)p0;
                float2 o1 = *(float2*)p1;
                c0 += o0.x; c1 += o0.y; c2 += o1.x; c3 += o1.y;
            }
            *(float2*)p0 = make_float2(c0, c1);
            *(float2*)p1 = make_float2(c2, c3);
        }
    }
}

// instantiations
using KernT = void(*)(const float*, const float*, const float*, const float*,
                      float*, int, int, int, int);
constexpr int DENSE_SMEM = 2 * 2 * (128 * 40 + 128 * 40) * 2;  // 81920 B
constexpr int H_SMEM     = 2 * 2 * (32 * 40 + 128 * 40) * 2;   // 51200 B

// ---------------------------------------------------------------------------
// RoPE (in-place on q and k).  layout [B,S,H,D]; pair (i, i+64)
// ---------------------------------------------------------------------------
__global__ void rope_kernel(float* __restrict__ q, float* __restrict__ k)
{
    const int total = Bn * Sn * Hn * (Dn / 2);
    int idx = blockIdx.x * blockDim.x + threadIdx.x;
    if (idx >= total) return;
    int i = idx & 63;
    int s = (idx >> 10) & (Sn - 1);
    float inv = (float)exp(-(double)i * 0.14391156831212788);  // ln(10000)/64
    float ang = (float)s * inv;
    float c, sn;
    sincosf(ang, &sn, &c);
    size_t base = ((size_t)(idx >> 6)) * 128;
    float q0 = q[base + i], q1 = q[base + i + 64];
    q[base + i]      = q0 * c - q1 * sn;
    q[base + i + 64] = q1 * c + q0 * sn;
    float k0 = k[base + i], k1 = k[base + i + 64];
    k[base + i]      = k0 * c - k1 * sn;
    k[base + i + 64] = k1 * c + k0 * sn;
}

// ---------------------------------------------------------------------------
// Flash attention, fp32. grid (S/64, H, B), 256 threads.
// ---------------------------------------------------------------------------
#define FLASH_SMEM_FLOATS (2 * 128 * 68 + 64 * 132 + 64 * 68 + 3 * 64)
#define FLASH_SMEM_BYTES  (FLASH_SMEM_FLOATS * 4)

__global__ void __launch_bounds__(256) flash_kernel(
    const float* __restrict__ Q, const float* __restrict__ K,
    const float* __restrict__ V, float* __restrict__ O)
{
    extern __shared__ float smf[];
    float (*Qs)[68]  = (float(*)[68])smf;
    float (*Ks)[68]  = (float(*)[68])(smf + 128 * 68);
    float (*Vs)[132] = (float(*)[132])(smf + 2 * 128 * 68);
    float (*Ps)[68]  = (float(*)[68])(smf + 2 * 128 * 68 + 64 * 132);
    float* m_s    = smf + 2 * 128 * 68 + 64 * 132 + 64 * 68;
    float* l_s    = m_s + 64;
    float* corr_s = l_s + 64;

    const int q0 = blockIdx.x * 64;
    const int h  = blockIdx.y;
    const int b  = blockIdx.z;
    const int tid = threadIdx.x;
    const int tx = tid & 15, ty = tid >> 4;
    const int r4 = tid >> 2;
    const int c4 = tid & 3;

    const float scale = 0.08838834764831845f;

    {
        const float4* src = (const float4*)(Q + ((((size_t)b * Sn + q0 + r4) * Hn + h) << 7));
#pragma unroll
        for (int f = 0; f < 8; f++) {
            int fi = c4 * 8 + f;
            float4 v = src[fi];
            int d = fi * 4;
            Qs[d + 0][r4] = v.x * scale;
            Qs[d + 1][r4] = v.y * scale;
            Qs[d + 2][r4] = v.z * scale;
            Qs[d + 3][r4] = v.w * scale;
        }
    }
    if (tid < 64) { m_s[tid] = NEG_BIG; l_s[tid] = 0.f; }

    float4 oa[8];
#pragma unroll
    for (int f = 0; f < 8; f++) oa[f] = make_float4(0.f, 0.f, 0.f, 0.f);

    for (int j0 = 0; j0 <= q0; j0 += 64) {
        __syncthreads();
        {
            const float* kb = K + ((((size_t)b * Sn + j0 + r4) * Hn + h) << 7);
            const float* vb = V + ((((size_t)b * Sn + j0 + r4) * Hn + h) << 7);
            const float4* ks = (const float4*)kb;
            const float4* vs = (const float4*)vb;
            float4* vrow = (float4*)&Vs[r4][0];
#pragma unroll
            for (int f = 0; f < 8; f++) {
                int fi = c4 * 8 + f;
                float4 kv = ks[fi];
                int d = fi * 4;
                Ks[d + 0][r4] = kv.x;
                Ks[d + 1][r4] = kv.y;
                Ks[d + 2][r4] = kv.z;
                Ks[d + 3][r4] = kv.w;
                vrow[fi] = vs[fi];
            }
        }
        __syncthreads();

        float s[4][4];
#pragma unroll
        for (int i = 0; i < 4; i++)
#pragma unroll
            for (int j = 0; j < 4; j++) s[i][j] = 0.f;

        for (int d = 0; d < 128; d++) {
            float4 qv = *(const float4*)&Qs[d][ty * 4];
            float4 kv = *(const float4*)&Ks[d][tx * 4];
            float qa[4] = {qv.x, qv.y, qv.z, qv.w};
            float ka[4] = {kv.x, kv.y, kv.z, kv.w};
#pragma unroll
            for (int i = 0; i < 4; i++)
#pragma unroll
                for (int j = 0; j < 4; j++)
                    s[i][j] = fmaf(qa[i], ka[j], s[i][j]);
        }

        if (j0 == q0) {
#pragma unroll
            for (int i = 0; i < 4; i++)
#pragma unroll
                for (int j = 0; j < 4; j++)
                    if (ty * 4 + i < tx * 4 + j) s[i][j] = NEG_BIG;
        }

#pragma unroll
        for (int i = 0; i < 4; i++) {
            float rm = fmaxf(fmaxf(s[i][0], s[i][1]), fmaxf(s[i][2], s[i][3]));
#pragma unroll
            for (int off = 8; off > 0; off >>= 1)
                rm = fmaxf(rm, __shfl_xor_sync(0xffffffffu, rm, off));
            if (tx == 0) {
                int row = ty * 4 + i;
                float mo = m_s[row];
                float mn = fmaxf(mo, rm);
                m_s[row] = mn;
                corr_s[row] = __expf(mo - mn);
            }
        }
        __syncthreads();

#pragma unroll
        for (int i = 0; i < 4; i++) {
            int row = ty * 4 + i;
            float mn = m_s[row];
            float rs = 0.f;
#pragma unroll
            for (int j = 0; j < 4; j++) {
                float p = __expf(s[i][j] - mn);
                Ps[row][tx * 4 + j] = p;
                rs += p;
            }
#pragma unroll
            for (int off = 8; off > 0; off >>= 1)
                rs += __shfl_xor_sync(0xffffffffu, rs, off);
            if (tx == 0) l_s[row] = l_s[row] * corr_s[row] + rs;
        }
        __syncthreads();

        {
            float cr = corr_s[r4];
#pragma unroll
            for (int f = 0; f < 8; f++) {
                oa[f].x *= cr; oa[f].y *= cr; oa[f].z *= cr; oa[f].w *= cr;
            }
            for (int j = 0; j < 64; j++) {
                float p = Ps[r4][j];
                const float4* vrow = (const float4*)&Vs[j][0];
#pragma unroll
                for (int f = 0; f < 8; f++) {
                    float4 v = vrow[c4 + 4 * f];
                    oa[f].x = fmaf(p, v.x, oa[f].x);
                    oa[f].y = fmaf(p, v.y, oa[f].y);
                    oa[f].z = fmaf(p, v.z, oa[f].z);
                    oa[f].w = fmaf(p, v.w, oa[f].w);
                }
            }
        }
    }

    {
        float invl = 1.f / l_s[r4];
        float4* dst = (float4*)(O + ((((size_t)b * Sn + q0 + r4) * Hn + h) << 7));
#pragma unroll
        for (int f = 0; f < 8; f++) {
            float4 v = oa[f];
            v.x *= invl; v.y *= invl; v.z *= invl; v.w *= invl;
            dst[c4 + 4 * f] = v;
        }
    }
}

// ---------------------------------------------------------------------------
extern "C" void kernel_launch(void* const* d_in, const int* in_sizes, int n_in,
                              void* d_out, int out_size)
{
    const float* x    = (const float*)d_in[0];
    const float* mask = (const float*)d_in[1];
    const float* Wq = (const float*)d_in[2];
    const float* bq = (const float*)d_in[3];
    const float* Aq = (const float*)d_in[4];
    const float* Bq = (const float*)d_in[5];
    const float* Wk = (const float*)d_in[6];
    const float* bk = (const float*)d_in[7];
    const float* Ak = (const float*)d_in[8];
    const float* Bk = (const float*)d_in[9];
    const float* Wv = (const float*)d_in[10];
    const float* bv = (const float*)d_in[11];
    const float* Av = (const float*)d_in[12];
    const float* Bv = (const float*)d_in[13];
    const float* Wo = (const float*)d_in[14];
    const float* bo = (const float*)d_in[15];
    const float* Ao = (const float*)d_in[16];
    const float* Bo = (const float*)d_in[17];
    float* out = (float*)d_out;

    float *gq, *gk, *gv, *go, *gh;
    cudaGetSymbolAddress((void**)&gq, g_q);
    cudaGetSymbolAddress((void**)&gk, g_k);
    cudaGetSymbolAddress((void**)&gv, g_v);
    cudaGetSymbolAddress((void**)&go, g_o);
    cudaGetSymbolAddress((void**)&gh, g_h);

    KernT tg_dense = tgemm_kernel<128, 128, 2, 8, 8>;
    KernT tg_h     = tgemm_kernel<32, 128, 1, 8, 4>;
    cudaFuncSetAttribute(tg_dense, cudaFuncAttributeMaxDynamicSharedMemorySize, DENSE_SMEM);
    cudaFuncSetAttribute(tg_h,     cudaFuncAttributeMaxDynamicSharedMemorySize, H_SMEM);

    dim3 gD(HDn / 128, Mn / 128);   // dense: (16, 32)
    dim3 gH(1, Mn / 32);            // low-rank h: (1, 128)

    // ---- Q ----
    tg_h<<<gH, 128, H_SMEM>>>(x, Aq, nullptr, mask, gh, Mn, NEn * Rn, En, 0);
    tg_dense<<<gD, 256, DENSE_SMEM>>>(x, Wq, bq, nullptr, gq, Mn, HDn, En, 0);
    tg_dense<<<gD, 256, DENSE_SMEM>>>(gh, Bq, nullptr, nullptr, gq, Mn, HDn, NEn * Rn, 1);
    // ---- K ----
    tg_h<<<gH, 128, H_SMEM>>>(x, Ak, nullptr, mask, gh, Mn, NEn * Rn, En, 0);
    tg_dense<<<gD, 256, DENSE_SMEM>>>(x, Wk, bk, nullptr, gk, Mn, HDn, En, 0);
    tg_dense<<<gD, 256, DENSE_SMEM>>>(gh, Bk, nullptr, nullptr, gk, Mn, HDn, NEn * Rn, 1);
    // ---- V ----
    tg_h<<<gH, 128, H_SMEM>>>(x, Av, nullptr, mask, gh, Mn, NEn * Rn, En, 0);
    tg_dense<<<gD, 256, DENSE_SMEM>>>(x, Wv, bv, nullptr, gv, Mn, HDn, En, 0);
    tg_dense<<<gD, 256, DENSE_SMEM>>>(gh, Bv, nullptr, nullptr, gv, Mn, HDn, NEn * Rn, 1);

    // ---- RoPE ----
    {
        int total = Bn * Sn * Hn * (Dn / 2);
        rope_kernel<<<(total + 255) / 256, 256>>>(gq, gk);
    }

    // ---- Attention ----
    cudaFuncSetAttribute(flash_kernel, cudaFuncAttributeMaxDynamicSharedMemorySize,
                         FLASH_SMEM_BYTES);
    flash_kernel<<<dim3(Sn / 64, Hn, Bn), 256, FLASH_SMEM_BYTES>>>(gq, gk, gv, go);

    // ---- Output projection ----
    tg_h<<<gH, 128, H_SMEM>>>(go, Ao, nullptr, mask, gh, Mn, NEn * Rn, HDn, 0);
    tg_dense<<<gD, 256, DENSE_SMEM>>>(go, Wo, bo, nullptr, out, Mn, En, HDn, 0);
    tg_dense<<<gD, 256, DENSE_SMEM>>>(gh, Bo, nullptr, nullptr, out, Mn, En, NEn * Rn, 1);
}

// round 7
// speedup vs baseline: 1.6800x; 1.0669x over previous
#include <cuda_runtime.h>
#include <cuda_bf16.h>
#include <cstdint>

// Problem constants
#define Bn  2
#define Sn  2048
#define En  2048
#define Hn  16
#define Dn  128
#define NEn 8
#define Rn  16
#define HDn 2048
#define Mn  4096            // B*S
#define NEG_BIG -3.0e38f

// ---------------- scratch (device globals: no cudaMalloc allowed) ----------
__device__ __align__(16) float g_q[(size_t)Mn * HDn];
__device__ __align__(16) float g_k[(size_t)Mn * HDn];
__device__ __align__(16) float g_v[(size_t)Mn * HDn];
__device__ __align__(16) float g_o[(size_t)Mn * HDn];
__device__ __align__(16) float g_h[3][(size_t)Mn * 128];

// bf16 hi/lo split operand storage
__device__ __align__(16) __nv_bfloat16 g_xhi[(size_t)Mn * En],  g_xlo[(size_t)Mn * En];
__device__ __align__(16) __nv_bfloat16 g_Whi[4][(size_t)HDn * En], g_Wlo[4][(size_t)HDn * En];
__device__ __align__(16) __nv_bfloat16 g_AXhi[4][(size_t)128 * En], g_AXlo[4][(size_t)128 * En];
__device__ __align__(16) __nv_bfloat16 g_BXhi[4][(size_t)HDn * 128], g_BXlo[4][(size_t)HDn * 128];
__device__ __align__(16) __nv_bfloat16 g_hhi[3][(size_t)Mn * 128], g_hlo[3][(size_t)Mn * 128];
__device__ __align__(16) __nv_bfloat16 g_ohi[(size_t)Mn * HDn], g_olo[(size_t)Mn * HDn];

// ---------------------------------------------------------------------------
// asm helpers
// ---------------------------------------------------------------------------
__device__ __forceinline__ void mma16(float* c, const uint32_t* a, const uint32_t* b) {
    asm("mma.sync.aligned.m16n8k16.row.col.f32.bf16.bf16.f32 "
        "{%0,%1,%2,%3}, {%4,%5,%6,%7}, {%8,%9}, {%0,%1,%2,%3};\n"
        : "+f"(c[0]), "+f"(c[1]), "+f"(c[2]), "+f"(c[3])
        : "r"(a[0]), "r"(a[1]), "r"(a[2]), "r"(a[3]), "r"(b[0]), "r"(b[1]));
}

__device__ __forceinline__ void ldsm4(uint32_t* r, uint32_t addr) {
    asm volatile(
        "ldmatrix.sync.aligned.m8n8.x4.shared.b16 {%0,%1,%2,%3}, [%4];"
        : "=r"(r[0]), "=r"(r[1]), "=r"(r[2]), "=r"(r[3]) : "r"(addr));
}

__device__ __forceinline__ void cp16(uint32_t saddr, const void* gaddr) {
    asm volatile("cp.async.cg.shared.global [%0], [%1], 16;\n"
                 :: "r"(saddr), "l"(gaddr));
}
__device__ __forceinline__ void cp_commit() {
    asm volatile("cp.async.commit_group;\n");
}
__device__ __forceinline__ void cp_wait1() {
    asm volatile("cp.async.wait_group 1;\n");
}
__device__ __forceinline__ void cp_wait0() {
    asm volatile("cp.async.wait_group 0;\n");
}

// ---------------------------------------------------------------------------
// f32 -> bf16 hi/lo split conversion (elementwise, float4-granular)
// ---------------------------------------------------------------------------
__global__ void cvt_kernel(const float* __restrict__ s,
                           __nv_bfloat16* __restrict__ hp,
                           __nv_bfloat16* __restrict__ lp, int n4)
{
    int i = blockIdx.x * blockDim.x + threadIdx.x;
    if (i >= n4) return;
    float4 v = ((const float4*)s)[i];
    __nv_bfloat162 h01 = __floats2bfloat162_rn(v.x, v.y);
    __nv_bfloat162 h23 = __floats2bfloat162_rn(v.z, v.w);
    float lx = v.x - __bfloat162float(h01.x);
    float ly = v.y - __bfloat162float(h01.y);
    float lz = v.z - __bfloat162float(h23.x);
    float lw = v.w - __bfloat162float(h23.y);
    __nv_bfloat162 l01 = __floats2bfloat162_rn(lx, ly);
    __nv_bfloat162 l23 = __floats2bfloat162_rn(lz, lw);
    uint2 hu, lu;
    hu.x = *(uint32_t*)&h01; hu.y = *(uint32_t*)&h23;
    lu.x = *(uint32_t*)&l01; lu.y = *(uint32_t*)&l23;
    ((uint2*)hp)[i] = hu;
    ((uint2*)lp)[i] = lu;
}

// ---------------------------------------------------------------------------
// tgemm2 (bf16x3, pre-split operands): C[M,N] = A @ B^T
//   A/B given as bf16 hi+lo arrays [rows][K]. Optional bias / mask / +=C.
//   blockIdx.z selects pointer set (batched q/k/v).
// BK = 32, cp.async double-buffered, ldmatrix frags, term-major mma order.
// ---------------------------------------------------------------------------
struct GArgs {
    const __nv_bfloat16* Ahi[3]; const __nv_bfloat16* Alo[3];
    const __nv_bfloat16* Bhi[3]; const __nv_bfloat16* Blo[3];
    const float* bias[3]; const float* mask[3]; float* C[3];
};

template<int BM, int BN, int MT, int NT, int NW>
__global__ void __launch_bounds__(NW * 32) tgemm2_kernel(
    GArgs g, int M, int N, int K, int accFlag)
{
    constexpr int NTHR  = NW * 32;
    constexpr int ROWB  = 80;                 // 40 bf16 per padded row
    constexpr int ABY   = BM * ROWB;
    constexpr int BBY   = BN * ROWB;
    constexpr int BUFB  = 2 * ABY + 2 * BBY;
    constexpr int WROWS = BM / (MT * 16);

    extern __shared__ char smraw[];
    const uint32_t sbase = (uint32_t)__cvta_generic_to_shared(smraw);

    const int z = blockIdx.z;
    const __nv_bfloat16* Ahi = g.Ahi[z];
    const __nv_bfloat16* Alo = g.Alo[z];
    const __nv_bfloat16* Bhi = g.Bhi[z];
    const __nv_bfloat16* Blo = g.Blo[z];
    const float* bias = g.bias[z];
    const float* mask = g.mask[z];
    float* C = g.C[z];

    const int bm = blockIdx.y * BM;
    const int bn = blockIdx.x * BN;
    const int tid  = threadIdx.x;
    const int lane = tid & 31;
    const int w    = tid >> 5;
    const int wm   = (w % WROWS) * (MT * 16);
    const int wn   = (w / WROWS) * (NT * 8);
    const int grp  = lane >> 2;
    const int qt   = lane & 3;

    const int a_row = ((lane >> 3) & 1) * 8 + (lane & 7);
    const int a_col = (lane >> 4) * 8;
    const int b_row = (lane >> 4) * 8 + (lane & 7);
    const int b_col = ((lane >> 3) & 1) * 8;

    float acc[MT][NT][4];
#pragma unroll
    for (int mt = 0; mt < MT; mt++)
#pragma unroll
        for (int nt = 0; nt < NT; nt++)
#pragma unroll
            for (int e = 0; e < 4; e++) acc[mt][nt][e] = 0.f;

    auto issue = [&](int it, int buf) {
        const int k0 = it << 5;
        const uint32_t sb = sbase + buf * BUFB;
#pragma unroll
        for (int i = tid; i < BM * 4; i += NTHR) {
            int row = i >> 2, c = i & 3;
            size_t go = (size_t)(bm + row) * K + k0 + c * 8;
            cp16(sb + row * ROWB + c * 16, Ahi + go);
            cp16(sb + ABY + row * ROWB + c * 16, Alo + go);
        }
#pragma unroll
        for (int i = tid; i < BN * 4; i += NTHR) {
            int row = i >> 2, c = i & 3;
            size_t go = (size_t)(bn + row) * K + k0 + c * 8;
            cp16(sb + 2 * ABY + row * ROWB + c * 16, Bhi + go);
            cp16(sb + 2 * ABY + BBY + row * ROWB + c * 16, Blo + go);
        }
        cp_commit();
    };

    issue(0, 0);

    const int nk = K >> 5;
    for (int it = 0; it < nk; it++) {
        const int buf = it & 1;
        if (it + 1 < nk) { issue(it + 1, buf ^ 1); cp_wait1(); }
        else             { cp_wait0(); }
        __syncthreads();

        const uint32_t aHi = sbase + buf * BUFB;
        const uint32_t aLo = aHi + ABY;
        const uint32_t bHi = aHi + 2 * ABY;
        const uint32_t bLo = bHi + BBY;

#pragma unroll
        for (int kk = 0; kk < 32; kk += 16) {
            uint32_t afH[MT][4], afL[MT][4];
#pragma unroll
            for (int mt = 0; mt < MT; mt++) {
                uint32_t off = (uint32_t)((wm + mt * 16 + a_row) * 40 + kk + a_col) * 2;
                ldsm4(afH[mt], aHi + off);
                ldsm4(afL[mt], aLo + off);
            }
#pragma unroll
            for (int nb = 0; nb < NT / 2; nb++) {
                uint32_t off = (uint32_t)((wn + nb * 16 + b_row) * 40 + kk + b_col) * 2;
                uint32_t bh[4], bl[4];
                ldsm4(bh, bHi + off);
                ldsm4(bl, bLo + off);
                // term-major: all accs for hi*lo, then lo*hi, then hi*hi
#pragma unroll
                for (int hf = 0; hf < 2; hf++)
#pragma unroll
                    for (int mt = 0; mt < MT; mt++)
                        mma16(acc[mt][nb * 2 + hf], afH[mt], &bl[hf * 2]);
#pragma unroll
                for (int hf = 0; hf < 2; hf++)
#pragma unroll
                    for (int mt = 0; mt < MT; mt++)
                        mma16(acc[mt][nb * 2 + hf], afL[mt], &bh[hf * 2]);
#pragma unroll
                for (int hf = 0; hf < 2; hf++)
#pragma unroll
                    for (int mt = 0; mt < MT; mt++)
                        mma16(acc[mt][nb * 2 + hf], afH[mt], &bh[hf * 2]);
            }
        }
        __syncthreads();   // all warps done with buf before it is refilled
    }

    // epilogue
#pragma unroll
    for (int mt = 0; mt < MT; mt++) {
#pragma unroll
        for (int nt = 0; nt < NT; nt++) {
            int m0 = bm + wm + mt * 16 + grp;
            int n  = bn + wn + nt * 8 + qt * 2;
            float c0 = acc[mt][nt][0], c1 = acc[mt][nt][1];
            float c2 = acc[mt][nt][2], c3 = acc[mt][nt][3];
            if (bias) {
                float b0 = bias[n], b1 = bias[n + 1];
                c0 += b0; c1 += b1; c2 += b0; c3 += b1;
            }
            if (mask) {   // h-GEMM: expert = n>>4 (R=16 contiguous)
                float s0 = mask[(size_t)m0 * NEn + (n >> 4)];
                float s1 = mask[(size_t)(m0 + 8) * NEn + (n >> 4)];
                c0 *= s0; c1 *= s0; c2 *= s1; c3 *= s1;
            }
            float* p0 = &C[(size_t)m0 * N + n];
            float* p1 = &C[(size_t)(m0 + 8) * N + n];
            if (accFlag) {
                float2 o0 = *(float2*)p0;
                float2 o1 = *(float2*)p1;
                c0 += o0.x; c1 += o0.y; c2 += o1.x; c3 += o1.y;
            }
            *(float2*)p0 = make_float2(c0, c1);
            *(float2*)p1 = make_float2(c2, c3);
        }
    }
}

using KernT = void(*)(GArgs, int, int, int, int);
constexpr int DENSE_SMEM = 2 * (2 * 128 * 80 + 2 * 128 * 80);   // 81920 B
constexpr int H_SMEM     = 2 * (2 * 32 * 80 + 2 * 128 * 80);    // 51200 B

// ---------------------------------------------------------------------------
// RoPE (in-place on q and k).  layout [B,S,H,D]; pair (i, i+64)
// ---------------------------------------------------------------------------
__global__ void rope_kernel(float* __restrict__ q, float* __restrict__ k)
{
    const int total = Bn * Sn * Hn * (Dn / 2);
    int idx = blockIdx.x * blockDim.x + threadIdx.x;
    if (idx >= total) return;
    int i = idx & 63;
    int s = (idx >> 10) & (Sn - 1);
    float inv = (float)exp(-(double)i * 0.14391156831212788);  // ln(10000)/64
    float ang = (float)s * inv;
    float c, sn;
    sincosf(ang, &sn, &c);
    size_t base = ((size_t)(idx >> 6)) * 128;
    float q0 = q[base + i], q1 = q[base + i + 64];
    q[base + i]      = q0 * c - q1 * sn;
    q[base + i + 64] = q1 * c + q0 * sn;
    float k0 = k[base + i], k1 = k[base + i + 64];
    k[base + i]      = k0 * c - k1 * sn;
    k[base + i + 64] = k1 * c + k0 * sn;
}

// ---------------------------------------------------------------------------
// Flash attention, fp32. grid (S/64, H, B), 256 threads.
// ---------------------------------------------------------------------------
#define FLASH_SMEM_FLOATS (2 * 128 * 68 + 64 * 132 + 64 * 68 + 3 * 64)
#define FLASH_SMEM_BYTES  (FLASH_SMEM_FLOATS * 4)

__global__ void __launch_bounds__(256) flash_kernel(
    const float* __restrict__ Q, const float* __restrict__ K,
    const float* __restrict__ V, float* __restrict__ O)
{
    extern __shared__ float smf[];
    float (*Qs)[68]  = (float(*)[68])smf;
    float (*Ks)[68]  = (float(*)[68])(smf + 128 * 68);
    float (*Vs)[132] = (float(*)[132])(smf + 2 * 128 * 68);
    float (*Ps)[68]  = (float(*)[68])(smf + 2 * 128 * 68 + 64 * 132);
    float* m_s    = smf + 2 * 128 * 68 + 64 * 132 + 64 * 68;
    float* l_s    = m_s + 64;
    float* corr_s = l_s + 64;

    const int q0 = blockIdx.x * 64;
    const int h  = blockIdx.y;
    const int b  = blockIdx.z;
    const int tid = threadIdx.x;
    const int tx = tid & 15, ty = tid >> 4;
    const int r4 = tid >> 2;
    const int c4 = tid & 3;

    const float scale = 0.08838834764831845f;

    {
        const float4* src = (const float4*)(Q + ((((size_t)b * Sn + q0 + r4) * Hn + h) << 7));
#pragma unroll
        for (int f = 0; f < 8; f++) {
            int fi = c4 * 8 + f;
            float4 v = src[fi];
            int d = fi * 4;
            Qs[d + 0][r4] = v.x * scale;
            Qs[d + 1][r4] = v.y * scale;
            Qs[d + 2][r4] = v.z * scale;
            Qs[d + 3][r4] = v.w * scale;
        }
    }
    if (tid < 64) { m_s[tid] = NEG_BIG; l_s[tid] = 0.f; }

    float4 oa[8];
#pragma unroll
    for (int f = 0; f < 8; f++) oa[f] = make_float4(0.f, 0.f, 0.f, 0.f);

    for (int j0 = 0; j0 <= q0; j0 += 64) {
        __syncthreads();
        {
            const float* kb = K + ((((size_t)b * Sn + j0 + r4) * Hn + h) << 7);
            const float* vb = V + ((((size_t)b * Sn + j0 + r4) * Hn + h) << 7);
            const float4* ks = (const float4*)kb;
            const float4* vs = (const float4*)vb;
            float4* vrow = (float4*)&Vs[r4][0];
#pragma unroll
            for (int f = 0; f < 8; f++) {
                int fi = c4 * 8 + f;
                float4 kv = ks[fi];
                int d = fi * 4;
                Ks[d + 0][r4] = kv.x;
                Ks[d + 1][r4] = kv.y;
                Ks[d + 2][r4] = kv.z;
                Ks[d + 3][r4] = kv.w;
                vrow[fi] = vs[fi];
            }
        }
        __syncthreads();

        float s[4][4];
#pragma unroll
        for (int i = 0; i < 4; i++)
#pragma unroll
            for (int j = 0; j < 4; j++) s[i][j] = 0.f;

        for (int d = 0; d < 128; d++) {
            float4 qv = *(const float4*)&Qs[d][ty * 4];
            float4 kv = *(const float4*)&Ks[d][tx * 4];
            float qa[4] = {qv.x, qv.y, qv.z, qv.w};
            float ka[4] = {kv.x, kv.y, kv.z, kv.w};
#pragma unroll
            for (int i = 0; i < 4; i++)
#pragma unroll
                for (int j = 0; j < 4; j++)
                    s[i][j] = fmaf(qa[i], ka[j], s[i][j]);
        }

        if (j0 == q0) {
#pragma unroll
            for (int i = 0; i < 4; i++)
#pragma unroll
                for (int j = 0; j < 4; j++)
                    if (ty * 4 + i < tx * 4 + j) s[i][j] = NEG_BIG;
        }

#pragma unroll
        for (int i = 0; i < 4; i++) {
            float rm = fmaxf(fmaxf(s[i][0], s[i][1]), fmaxf(s[i][2], s[i][3]));
#pragma unroll
            for (int off = 8; off > 0; off >>= 1)
                rm = fmaxf(rm, __shfl_xor_sync(0xffffffffu, rm, off));
            if (tx == 0) {
                int row = ty * 4 + i;
                float mo = m_s[row];
                float mn = fmaxf(mo, rm);
                m_s[row] = mn;
                corr_s[row] = __expf(mo - mn);
            }
        }
        __syncthreads();

#pragma unroll
        for (int i = 0; i < 4; i++) {
            int row = ty * 4 + i;
            float mn = m_s[row];
            float rs = 0.f;
#pragma unroll
            for (int j = 0; j < 4; j++) {
                float p = __expf(s[i][j] - mn);
                Ps[row][tx * 4 + j] = p;
                rs += p;
            }
#pragma unroll
            for (int off = 8; off > 0; off >>= 1)
                rs += __shfl_xor_sync(0xffffffffu, rs, off);
            if (tx == 0) l_s[row] = l_s[row] * corr_s[row] + rs;
        }
        __syncthreads();

        {
            float cr = corr_s[r4];
#pragma unroll
            for (int f = 0; f < 8; f++) {
                oa[f].x *= cr; oa[f].y *= cr; oa[f].z *= cr; oa[f].w *= cr;
            }
            for (int j = 0; j < 64; j++) {
                float p = Ps[r4][j];
                const float4* vrow = (const float4*)&Vs[j][0];
#pragma unroll
                for (int f = 0; f < 8; f++) {
                    float4 v = vrow[c4 + 4 * f];
                    oa[f].x = fmaf(p, v.x, oa[f].x);
                    oa[f].y = fmaf(p, v.y, oa[f].y);
                    oa[f].z = fmaf(p, v.z, oa[f].z);
                    oa[f].w = fmaf(p, v.w, oa[f].w);
                }
            }
        }
    }

    {
        float invl = 1.f / l_s[r4];
        float4* dst = (float4*)(O + ((((size_t)b * Sn + q0 + r4) * Hn + h) << 7));
#pragma unroll
        for (int f = 0; f < 8; f++) {
            float4 v = oa[f];
            v.x *= invl; v.y *= invl; v.z *= invl; v.w *= invl;
            dst[c4 + 4 * f] = v;
        }
    }
}

// ---------------------------------------------------------------------------
extern "C" void kernel_launch(void* const* d_in, const int* in_sizes, int n_in,
                              void* d_out, int out_size)
{
    const float* x    = (const float*)d_in[0];
    const float* mask = (const float*)d_in[1];
    const float* Wp[4] = {(const float*)d_in[2], (const float*)d_in[6],
                          (const float*)d_in[10], (const float*)d_in[14]};
    const float* bp[4] = {(const float*)d_in[3], (const float*)d_in[7],
                          (const float*)d_in[11], (const float*)d_in[15]};
    const float* Ap[4] = {(const float*)d_in[4], (const float*)d_in[8],
                          (const float*)d_in[12], (const float*)d_in[16]};
    const float* Bp[4] = {(const float*)d_in[5], (const float*)d_in[9],
                          (const float*)d_in[13], (const float*)d_in[17]};
    float* out = (float*)d_out;

    float *gq, *gk, *gv, *go;
    cudaGetSymbolAddress((void**)&gq, g_q);
    cudaGetSymbolAddress((void**)&gk, g_k);
    cudaGetSymbolAddress((void**)&gv, g_v);
    cudaGetSymbolAddress((void**)&go, g_o);
    float* gqkv[3] = {gq, gk, gv};

    float* gh[3];
    __nv_bfloat16 *xhi, *xlo, *ohi, *olo;
    __nv_bfloat16 *Whi[4], *Wlo[4], *AXhi[4], *AXlo[4], *BXhi[4], *BXlo[4];
    __nv_bfloat16 *hhi[3], *hlo[3];
    {
        char *p_h, *p_xh, *p_xl, *p_Wh, *p_Wl, *p_Ah, *p_Al, *p_Bh, *p_Bl, *p_hh, *p_hl, *p_oh, *p_ol;
        cudaGetSymbolAddress((void**)&p_h,  g_h);
        cudaGetSymbolAddress((void**)&p_xh, g_xhi);
        cudaGetSymbolAddress((void**)&p_xl, g_xlo);
        cudaGetSymbolAddress((void**)&p_Wh, g_Whi);
        cudaGetSymbolAddress((void**)&p_Wl, g_Wlo);
        cudaGetSymbolAddress((void**)&p_Ah, g_AXhi);
        cudaGetSymbolAddress((void**)&p_Al, g_AXlo);
        cudaGetSymbolAddress((void**)&p_Bh, g_BXhi);
        cudaGetSymbolAddress((void**)&p_Bl, g_BXlo);
        cudaGetSymbolAddress((void**)&p_hh, g_hhi);
        cudaGetSymbolAddress((void**)&p_hl, g_hlo);
        cudaGetSymbolAddress((void**)&p_oh, g_ohi);
        cudaGetSymbolAddress((void**)&p_ol, g_olo);
        for (int i = 0; i < 3; i++) {
            gh[i]  = (float*)(p_h + (size_t)i * Mn * 128 * 4);
            hhi[i] = (__nv_bfloat16*)(p_hh + (size_t)i * Mn * 128 * 2);
            hlo[i] = (__nv_bfloat16*)(p_hl + (size_t)i * Mn * 128 * 2);
        }
        xhi = (__nv_bfloat16*)p_xh; xlo = (__nv_bfloat16*)p_xl;
        ohi = (__nv_bfloat16*)p_oh; olo = (__nv_bfloat16*)p_ol;
        for (int i = 0; i < 4; i++) {
            Whi[i]  = (__nv_bfloat16*)(p_Wh + (size_t)i * HDn * En * 2);
            Wlo[i]  = (__nv_bfloat16*)(p_Wl + (size_t)i * HDn * En * 2);
            AXhi[i] = (__nv_bfloat16*)(p_Ah + (size_t)i * 128 * En * 2);
            AXlo[i] = (__nv_bfloat16*)(p_Al + (size_t)i * 128 * En * 2);
            BXhi[i] = (__nv_bfloat16*)(p_Bh + (size_t)i * HDn * 128 * 2);
            BXlo[i] = (__nv_bfloat16*)(p_Bl + (size_t)i * HDn * 128 * 2);
        }
    }

    KernT tg_d = tgemm2_kernel<128, 128, 2, 8, 8>;
    KernT tg_h = tgemm2_kernel<32, 128, 1, 8, 4>;
    cudaFuncSetAttribute(tg_d, cudaFuncAttributeMaxDynamicSharedMemorySize, DENSE_SMEM);
    cudaFuncSetAttribute(tg_h, cudaFuncAttributeMaxDynamicSharedMemorySize, H_SMEM);
    cudaFuncSetAttribute(flash_kernel, cudaFuncAttributeMaxDynamicSharedMemorySize,
                         FLASH_SMEM_BYTES);

    auto cvt = [&](const float* s, __nv_bfloat16* h, __nv_bfloat16* l, size_t n) {
        int n4 = (int)(n / 4);
        cvt_kernel<<<(n4 + 255) / 256, 256>>>(s, h, l, n4);
    };

    // ---- conversions ----
    cvt(x, xhi, xlo, (size_t)Mn * En);
    for (int i = 0; i < 4; i++) {
        cvt(Wp[i], Whi[i], Wlo[i], (size_t)HDn * En);
        cvt(Ap[i], AXhi[i], AXlo[i], (size_t)128 * En);
        cvt(Bp[i], BXhi[i], BXlo[i], (size_t)HDn * 128);
    }

    GArgs a;
    // ---- h projections (q,k,v), batched z=3 ----
    for (int i = 0; i < 3; i++) {
        a.Ahi[i] = xhi; a.Alo[i] = xlo;
        a.Bhi[i] = AXhi[i]; a.Blo[i] = AXlo[i];
        a.bias[i] = nullptr; a.mask[i] = mask; a.C[i] = gh[i];
    }
    tg_h<<<dim3(1, Mn / 32, 3), 128, H_SMEM>>>(a, Mn, 128, En, 0);
    for (int i = 0; i < 3; i++) cvt(gh[i], hhi[i], hlo[i], (size_t)Mn * 128);

    // ---- dense q,k,v, batched z=3 ----
    for (int i = 0; i < 3; i++) {
        a.Ahi[i] = xhi; a.Alo[i] = xlo;
        a.Bhi[i] = Whi[i]; a.Blo[i] = Wlo[i];
        a.bias[i] = bp[i]; a.mask[i] = nullptr; a.C[i] = gqkv[i];
    }
    tg_d<<<dim3(HDn / 128, Mn / 128, 3), 256, DENSE_SMEM>>>(a, Mn, HDn, En, 0);

    // ---- low-rank B accumulate q,k,v, batched z=3 ----
    for (int i = 0; i < 3; i++) {
        a.Ahi[i] = hhi[i]; a.Alo[i] = hlo[i];
        a.Bhi[i] = BXhi[i]; a.Blo[i] = BXlo[i];
        a.bias[i] = nullptr; a.mask[i] = nullptr; a.C[i] = gqkv[i];
    }
    tg_d<<<dim3(HDn / 128, Mn / 128, 3), 256, DENSE_SMEM>>>(a, Mn, HDn, 128, 1);

    // ---- RoPE ----
    {
        int total = Bn * Sn * Hn * (Dn / 2);
        rope_kernel<<<(total + 255) / 256, 256>>>(gq, gk);
    }

    // ---- Attention ----
    flash_kernel<<<dim3(Sn / 64, Hn, Bn), 256, FLASH_SMEM_BYTES>>>(gq, gk, gv, go);

    // ---- Output projection ----
    cvt(go, ohi, olo, (size_t)Mn * HDn);
    a.Ahi[0] = ohi; a.Alo[0] = olo;
    a.Bhi[0] = AXhi[3]; a.Blo[0] = AXlo[3];
    a.bias[0] = nullptr; a.mask[0] = mask; a.C[0] = gh[0];
    tg_h<<<dim3(1, Mn / 32, 1), 128, H_SMEM>>>(a, Mn, 128, HDn, 0);
    cvt(gh[0], hhi[0], hlo[0], (size_t)Mn * 128);

    a.Ahi[0] = ohi; a.Alo[0] = olo;
    a.Bhi[0] = Whi[3]; a.Blo[0] = Wlo[3];
    a.bias[0] = bp[3]; a.mask[0] = nullptr; a.C[0] = out;
    tg_d<<<dim3(En / 128, Mn / 128, 1), 256, DENSE_SMEM>>>(a, Mn, En, HDn, 0);

    a.Ahi[0] = hhi[0]; a.Alo[0] = hlo[0];
    a.Bhi[0] = BXhi[3]; a.Blo[0] = BXlo[3];
    a.bias[0] = nullptr; a.mask[0] = nullptr; a.C[0] = out;
    tg_d<<<dim3(En / 128, Mn / 128, 1), 256, DENSE_SMEM>>>(a, Mn, En, 128, 1);
}

// round 9
// speedup vs baseline: 3.3010x; 1.9649x over previous
#include <cuda_runtime.h>
#include <cuda_bf16.h>
#include <cstdint>

// Problem constants
#define Bn  2
#define Sn  2048
#define En  2048
#define Hn  16
#define Dn  128
#define NEn 8
#define Rn  16
#define HDn 2048
#define Mn  4096            // B*S
#define NEG_BIG -3.0e38f

// ---------------- scratch (device globals: no cudaMalloc allowed) ----------
__device__ __align__(16) float g_q[(size_t)Mn * HDn];
__device__ __align__(16) float g_k[(size_t)Mn * HDn];
__device__ __align__(16) float g_v[(size_t)Mn * HDn];
__device__ __align__(16) float g_o[(size_t)Mn * HDn];
__device__ __align__(16) float g_h[3][(size_t)Mn * 128];

// bf16 hi/lo split operand storage
__device__ __align__(16) __nv_bfloat16 g_xhi[(size_t)Mn * En],  g_xlo[(size_t)Mn * En];
__device__ __align__(16) __nv_bfloat16 g_Whi[4][(size_t)HDn * En], g_Wlo[4][(size_t)HDn * En];
__device__ __align__(16) __nv_bfloat16 g_AXhi[4][(size_t)128 * En], g_AXlo[4][(size_t)128 * En];
__device__ __align__(16) __nv_bfloat16 g_BXhi[4][(size_t)HDn * 128], g_BXlo[4][(size_t)HDn * 128];
__device__ __align__(16) __nv_bfloat16 g_hhi[3][(size_t)Mn * 128], g_hlo[3][(size_t)Mn * 128];
__device__ __align__(16) __nv_bfloat16 g_ohi[(size_t)Mn * HDn], g_olo[(size_t)Mn * HDn];
// flash operands: q/k rope'd splits [B,S,H,D]; v^T splits [B,H,D,S]
__device__ __align__(16) __nv_bfloat16 g_qshi[(size_t)Mn * HDn], g_qslo[(size_t)Mn * HDn];
__device__ __align__(16) __nv_bfloat16 g_kshi[(size_t)Mn * HDn], g_kslo[(size_t)Mn * HDn];
__device__ __align__(16) __nv_bfloat16 g_vthi[(size_t)Mn * HDn], g_vtlo[(size_t)Mn * HDn];

// ---------------------------------------------------------------------------
// asm helpers
// ---------------------------------------------------------------------------
__device__ __forceinline__ void mma16(float* c, const uint32_t* a, const uint32_t* b) {
    asm("mma.sync.aligned.m16n8k16.row.col.f32.bf16.bf16.f32 "
        "{%0,%1,%2,%3}, {%4,%5,%6,%7}, {%8,%9}, {%0,%1,%2,%3};\n"
        : "+f"(c[0]), "+f"(c[1]), "+f"(c[2]), "+f"(c[3])
        : "r"(a[0]), "r"(a[1]), "r"(a[2]), "r"(a[3]), "r"(b[0]), "r"(b[1]));
}

__device__ __forceinline__ void ldsm4(uint32_t* r, uint32_t addr) {
    asm volatile(
        "ldmatrix.sync.aligned.m8n8.x4.shared.b16 {%0,%1,%2,%3}, [%4];"
        : "=r"(r[0]), "=r"(r[1]), "=r"(r[2]), "=r"(r[3]) : "r"(addr));
}

__device__ __forceinline__ void cp16(uint32_t saddr, const void* gaddr) {
    asm volatile("cp.async.cg.shared.global [%0], [%1], 16;\n" :: "r"(saddr), "l"(gaddr));
}
__device__ __forceinline__ void cp_commit() { asm volatile("cp.async.commit_group;\n"); }
__device__ __forceinline__ void cp_wait1()  { asm volatile("cp.async.wait_group 1;\n"); }
__device__ __forceinline__ void cp_wait0()  { asm volatile("cp.async.wait_group 0;\n"); }

__device__ __forceinline__ float ex2(float x) {
    float r;
    asm("ex2.approx.f32 %0, %1;" : "=f"(r) : "f"(x));
    return r;
}

// split a,b into packed bf16x2 hi and lo fragments
__device__ __forceinline__ void packsplit(float a, float b, uint32_t& hi, uint32_t& lo) {
    __nv_bfloat162 h = __floats2bfloat162_rn(a, b);
    float ra = a - __bfloat162float(h.x);
    float rb = b - __bfloat162float(h.y);
    __nv_bfloat162 l = __floats2bfloat162_rn(ra, rb);
    hi = *(uint32_t*)&h;
    lo = *(uint32_t*)&l;
}

// ---------------------------------------------------------------------------
// f32 -> bf16 hi/lo split conversion (elementwise, float4-granular)
// ---------------------------------------------------------------------------
__global__ void cvt_kernel(const float* __restrict__ s,
                           __nv_bfloat16* __restrict__ hp,
                           __nv_bfloat16* __restrict__ lp, int n4)
{
    int i = blockIdx.x * blockDim.x + threadIdx.x;
    if (i >= n4) return;
    float4 v = ((const float4*)s)[i];
    uint32_t h01, l01, h23, l23;
    packsplit(v.x, v.y, h01, l01);
    packsplit(v.z, v.w, h23, l23);
    ((uint2*)hp)[i] = make_uint2(h01, h23);
    ((uint2*)lp)[i] = make_uint2(l01, l23);
}

// ---------------------------------------------------------------------------
// tgemm2 (bf16x3, pre-split operands): C[M,N] = A @ B^T   (unchanged from R7)
// ---------------------------------------------------------------------------
struct GArgs {
    const __nv_bfloat16* Ahi[3]; const __nv_bfloat16* Alo[3];
    const __nv_bfloat16* Bhi[3]; const __nv_bfloat16* Blo[3];
    const float* bias[3]; const float* mask[3]; float* C[3];
};

template<int BM, int BN, int MT, int NT, int NW>
__global__ void __launch_bounds__(NW * 32) tgemm2_kernel(
    GArgs g, int M, int N, int K, int accFlag)
{
    constexpr int NTHR  = NW * 32;
    constexpr int ROWB  = 80;                 // 40 bf16 per padded row
    constexpr int ABY   = BM * ROWB;
    constexpr int BBY   = BN * ROWB;
    constexpr int BUFB  = 2 * ABY + 2 * BBY;
    constexpr int WROWS = BM / (MT * 16);

    extern __shared__ char smraw[];
    const uint32_t sbase = (uint32_t)__cvta_generic_to_shared(smraw);

    const int z = blockIdx.z;
    const __nv_bfloat16* Ahi = g.Ahi[z];
    const __nv_bfloat16* Alo = g.Alo[z];
    const __nv_bfloat16* Bhi = g.Bhi[z];
    const __nv_bfloat16* Blo = g.Blo[z];
    const float* bias = g.bias[z];
    const float* mask = g.mask[z];
    float* C = g.C[z];

    const int bm = blockIdx.y * BM;
    const int bn = blockIdx.x * BN;
    const int tid  = threadIdx.x;
    const int lane = tid & 31;
    const int w    = tid >> 5;
    const int wm   = (w % WROWS) * (MT * 16);
    const int wn   = (w / WROWS) * (NT * 8);
    const int grp  = lane >> 2;
    const int qt   = lane & 3;

    const int a_row = ((lane >> 3) & 1) * 8 + (lane & 7);
    const int a_col = (lane >> 4) * 8;
    const int b_row = (lane >> 4) * 8 + (lane & 7);
    const int b_col = ((lane >> 3) & 1) * 8;

    float acc[MT][NT][4];
#pragma unroll
    for (int mt = 0; mt < MT; mt++)
#pragma unroll
        for (int nt = 0; nt < NT; nt++)
#pragma unroll
            for (int e = 0; e < 4; e++) acc[mt][nt][e] = 0.f;

    auto issue = [&](int it, int buf) {
        const int k0 = it << 5;
        const uint32_t sb = sbase + buf * BUFB;
#pragma unroll
        for (int i = tid; i < BM * 4; i += NTHR) {
            int row = i >> 2, c = i & 3;
            size_t go = (size_t)(bm + row) * K + k0 + c * 8;
            cp16(sb + row * ROWB + c * 16, Ahi + go);
            cp16(sb + ABY + row * ROWB + c * 16, Alo + go);
        }
#pragma unroll
        for (int i = tid; i < BN * 4; i += NTHR) {
            int row = i >> 2, c = i & 3;
            size_t go = (size_t)(bn + row) * K + k0 + c * 8;
            cp16(sb + 2 * ABY + row * ROWB + c * 16, Bhi + go);
            cp16(sb + 2 * ABY + BBY + row * ROWB + c * 16, Blo + go);
        }
        cp_commit();
    };

    issue(0, 0);

    const int nk = K >> 5;
    for (int it = 0; it < nk; it++) {
        const int buf = it & 1;
        if (it + 1 < nk) { issue(it + 1, buf ^ 1); cp_wait1(); }
        else             { cp_wait0(); }
        __syncthreads();

        const uint32_t aHi = sbase + buf * BUFB;
        const uint32_t aLo = aHi + ABY;
        const uint32_t bHi = aHi + 2 * ABY;
        const uint32_t bLo = bHi + BBY;

#pragma unroll
        for (int kk = 0; kk < 32; kk += 16) {
            uint32_t afH[MT][4], afL[MT][4];
#pragma unroll
            for (int mt = 0; mt < MT; mt++) {
                uint32_t off = (uint32_t)((wm + mt * 16 + a_row) * 40 + kk + a_col) * 2;
                ldsm4(afH[mt], aHi + off);
                ldsm4(afL[mt], aLo + off);
            }
#pragma unroll
            for (int nb = 0; nb < NT / 2; nb++) {
                uint32_t off = (uint32_t)((wn + nb * 16 + b_row) * 40 + kk + b_col) * 2;
                uint32_t bh[4], bl[4];
                ldsm4(bh, bHi + off);
                ldsm4(bl, bLo + off);
#pragma unroll
                for (int hf = 0; hf < 2; hf++)
#pragma unroll
                    for (int mt = 0; mt < MT; mt++)
                        mma16(acc[mt][nb * 2 + hf], afH[mt], &bl[hf * 2]);
#pragma unroll
                for (int hf = 0; hf < 2; hf++)
#pragma unroll
                    for (int mt = 0; mt < MT; mt++)
                        mma16(acc[mt][nb * 2 + hf], afL[mt], &bh[hf * 2]);
#pragma unroll
                for (int hf = 0; hf < 2; hf++)
#pragma unroll
                    for (int mt = 0; mt < MT; mt++)
                        mma16(acc[mt][nb * 2 + hf], afH[mt], &bh[hf * 2]);
            }
        }
        __syncthreads();
    }

#pragma unroll
    for (int mt = 0; mt < MT; mt++) {
#pragma unroll
        for (int nt = 0; nt < NT; nt++) {
            int m0 = bm + wm + mt * 16 + grp;
            int n  = bn + wn + nt * 8 + qt * 2;
            float c0 = acc[mt][nt][0], c1 = acc[mt][nt][1];
            float c2 = acc[mt][nt][2], c3 = acc[mt][nt][3];
            if (bias) {
                float b0 = bias[n], b1 = bias[n + 1];
                c0 += b0; c1 += b1; c2 += b0; c3 += b1;
            }
            if (mask) {
                float s0 = mask[(size_t)m0 * NEn + (n >> 4)];
                float s1 = mask[(size_t)(m0 + 8) * NEn + (n >> 4)];
                c0 *= s0; c1 *= s0; c2 *= s1; c3 *= s1;
            }
            float* p0 = &C[(size_t)m0 * N + n];
            float* p1 = &C[(size_t)(m0 + 8) * N + n];
            if (accFlag) {
                float2 o0 = *(float2*)p0;
                float2 o1 = *(float2*)p1;
                c0 += o0.x; c1 += o0.y; c2 += o1.x; c3 += o1.y;
            }
            *(float2*)p0 = make_float2(c0, c1);
            *(float2*)p1 = make_float2(c2, c3);
        }
    }
}

using KernT = void(*)(GArgs, int, int, int, int);
constexpr int DENSE_SMEM = 2 * (2 * 128 * 80 + 2 * 128 * 80);   // 81920 B
constexpr int H_SMEM     = 2 * (2 * 32 * 80 + 2 * 128 * 80);    // 51200 B

// ---------------------------------------------------------------------------
// RoPE + bf16 hi/lo split.  q gets *log2(e)/sqrt(D) folded in (for exp2 softmax)
// ---------------------------------------------------------------------------
__global__ void rope_split_kernel(const float* __restrict__ q, const float* __restrict__ k,
                                  __nv_bfloat16* __restrict__ qhi, __nv_bfloat16* __restrict__ qlo,
                                  __nv_bfloat16* __restrict__ khi, __nv_bfloat16* __restrict__ klo)
{
    const int total = Bn * Sn * Hn * (Dn / 2);
    int idx = blockIdx.x * blockDim.x + threadIdx.x;
    if (idx >= total) return;
    int i = idx & 63;
    int s = (idx >> 10) & (Sn - 1);
    float inv = (float)exp(-(double)i * 0.14391156831212788);  // ln(10000)/64
    float ang = (float)s * inv;
    float c, sn;
    sincosf(ang, &sn, &c);
    size_t base = ((size_t)(idx >> 6)) * 128;
    const float QSC = 0.12751743f;   // log2(e)/sqrt(128)

    float q0 = q[base + i], q1 = q[base + i + 64];
    float r0 = (q0 * c - q1 * sn) * QSC;
    float r1 = (q1 * c + q0 * sn) * QSC;
    __nv_bfloat16 h0 = __float2bfloat16_rn(r0);
    __nv_bfloat16 h1 = __float2bfloat16_rn(r1);
    qhi[base + i] = h0;  qlo[base + i] = __float2bfloat16_rn(r0 - __bfloat162float(h0));
    qhi[base + i + 64] = h1; qlo[base + i + 64] = __float2bfloat16_rn(r1 - __bfloat162float(h1));

    float k0 = k[base + i], k1 = k[base + i + 64];
    float t0 = k0 * c - k1 * sn;
    float t1 = k1 * c + k0 * sn;
    __nv_bfloat16 g0 = __float2bfloat16_rn(t0);
    __nv_bfloat16 g1 = __float2bfloat16_rn(t1);
    khi[base + i] = g0;  klo[base + i] = __float2bfloat16_rn(t0 - __bfloat162float(g0));
    khi[base + i + 64] = g1; klo[base + i + 64] = __float2bfloat16_rn(t1 - __bfloat162float(g1));
}

// ---------------------------------------------------------------------------
// V split + transpose:  v [B,S,H,D] f32  ->  vt{hi,lo} [B,H,D,S] bf16
// ---------------------------------------------------------------------------
__global__ void vsplit_kernel(const float* __restrict__ v,
                              __nv_bfloat16* __restrict__ vthi,
                              __nv_bfloat16* __restrict__ vtlo)
{
    __shared__ float tile[32][33];
    const int bh = blockIdx.z;        // b*Hn + h
    const int b  = bh >> 4, h = bh & 15;
    const int s0 = blockIdx.x * 32;
    const int d0 = blockIdx.y * 32;
    const int tx = threadIdx.x, ty = threadIdx.y;

#pragma unroll
    for (int r = 0; r < 4; r++) {
        int s = s0 + ty + r * 8;
        tile[ty + r * 8][tx] = v[(((size_t)b * Sn + s) * Hn + h) * 128 + d0 + tx];
    }
    __syncthreads();
#pragma unroll
    for (int r = 0; r < 4; r++) {
        int d = d0 + ty + r * 8;
        float val = tile[tx][ty + r * 8];
        __nv_bfloat16 hi = __float2bfloat16_rn(val);
        size_t o = ((size_t)bh * 128 + d) * Sn + s0 + tx;
        vthi[o] = hi;
        vtlo[o] = __float2bfloat16_rn(val - __bfloat162float(hi));
    }
}

// ---------------------------------------------------------------------------
// Flash attention, bf16x3 tensor cores.
//   grid (S/128, H, B) [x reversed for causal balance], 256 threads (8 warps).
//   Warp w owns q-rows [w*16, w*16+16). Tiles of 64 keys. Q resident in smem,
//   K/V^T cp.async double-buffered. Softmax fp32 in registers (exp2, FA2-style
//   accumulator->A-fragment reuse for P).
// ---------------------------------------------------------------------------
#define FQH 0
#define FQL 34816
#define FKH(b) (69632 + (b) * 34816)
#define FKL(b) (FKH(b) + 17408)
#define FVH(b) (139264 + (b) * 36864)
#define FVL(b) (FVH(b) + 18432)
#define FLASH_SMEM 212992

__global__ void __launch_bounds__(256, 1) flash_kernel(
    const __nv_bfloat16* __restrict__ Qhi, const __nv_bfloat16* __restrict__ Qlo,
    const __nv_bfloat16* __restrict__ Khi, const __nv_bfloat16* __restrict__ Klo,
    const __nv_bfloat16* __restrict__ Vthi, const __nv_bfloat16* __restrict__ Vtlo,
    float* __restrict__ O)
{
    extern __shared__ char smraw[];
    const uint32_t sb = (uint32_t)__cvta_generic_to_shared(smraw);

    const int qTile = gridDim.x - 1 - blockIdx.x;   // heavy CTAs first
    const int q0 = qTile * 128;
    const int h  = blockIdx.y;
    const int b  = blockIdx.z;
    const int tid  = threadIdx.x;
    const int lane = tid & 31;
    const int w    = tid >> 5;
    const int w16  = w * 16;
    const int grp  = lane >> 2;
    const int qt   = lane & 3;

    const int a_row = ((lane >> 3) & 1) * 8 + (lane & 7);
    const int a_col = (lane >> 4) * 8;
    const int b_row = (lane >> 4) * 8 + (lane & 7);
    const int b_col = ((lane >> 3) & 1) * 8;

    // K tile fill (64 rows x 256B, pitch 272B)
    auto fillK = [&](int j0, int buf) {
        for (int i = tid; i < 1024; i += 256) {
            int row = i >> 4, c = i & 15;
            size_t gg = (((size_t)b * Sn + j0 + row) * Hn + h) * 128 + c * 8;
            uint32_t so = row * 272 + c * 16;
            cp16(sb + FKH(buf) + so, Khi + gg);
            cp16(sb + FKL(buf) + so, Klo + gg);
        }
    };
    // V^T tile fill (128 rows x 128B, pitch 144B)
    auto fillV = [&](int j0, int buf) {
        for (int i = tid; i < 1024; i += 256) {
            int row = i >> 3, c = i & 7;
            size_t gg = (((size_t)(b * Hn + h)) * 128 + row) * Sn + j0 + c * 8;
            uint32_t so = row * 144 + c * 16;
            cp16(sb + FVH(buf) + so, Vthi + gg);
            cp16(sb + FVL(buf) + so, Vtlo + gg);
        }
    };

    // Q fill (128 rows, pitch 272B) + tile 0, one group
    for (int i = tid; i < 2048; i += 256) {
        int row = i >> 4, c = i & 15;
        size_t gg = (((size_t)b * Sn + q0 + row) * Hn + h) * 128 + c * 8;
        uint32_t so = row * 272 + c * 16;
        cp16(sb + FQH + so, Qhi + gg);
        cp16(sb + FQL + so, Qlo + gg);
    }
    fillK(0, 0);
    fillV(0, 0);
    cp_commit();

    float o[16][4];
#pragma unroll
    for (int t = 0; t < 16; t++)
#pragma unroll
        for (int e = 0; e < 4; e++) o[t][e] = 0.f;
    float run_m0 = NEG_BIG, run_m1 = NEG_BIG;
    float run_l0 = 0.f, run_l1 = 0.f;

    const int ntiles = qTile * 2 + 2;
    for (int t = 0; t < ntiles; t++) {
        const int buf = t & 1;
        const int j0 = t * 64;
        if (t + 1 < ntiles) {
            fillK((t + 1) * 64, buf ^ 1);
            fillV((t + 1) * 64, buf ^ 1);
            cp_commit();
            cp_wait1();
        } else {
            cp_wait0();
        }
        __syncthreads();

        // ---- S = Q K^T (bf16x3) ----
        float s[8][4];
#pragma unroll
        for (int tt = 0; tt < 8; tt++)
#pragma unroll
            for (int e = 0; e < 4; e++) s[tt][e] = 0.f;

        const uint32_t kh = FKH(buf), kl = FKL(buf);
#pragma unroll
        for (int kk = 0; kk < 8; kk++) {
            uint32_t qh[4], ql[4];
            uint32_t qoff = (uint32_t)((w16 + a_row) * 136 + kk * 16 + a_col) * 2;
            ldsm4(qh, sb + FQH + qoff);
            ldsm4(ql, sb + FQL + qoff);
#pragma unroll
            for (int nb = 0; nb < 4; nb++) {
                uint32_t bh[4], bl[4];
                uint32_t boff = (uint32_t)((nb * 16 + b_row) * 136 + kk * 16 + b_col) * 2;
                ldsm4(bh, sb + kh + boff);
                ldsm4(bl, sb + kl + boff);
#pragma unroll
                for (int hf = 0; hf < 2; hf++) {
                    float* c = s[nb * 2 + hf];
                    mma16(c, qh, &bl[hf * 2]);
                    mma16(c, ql, &bh[hf * 2]);
                    mma16(c, qh, &bh[hf * 2]);
                }
            }
        }

        // ---- causal mask (only near the diagonal) ----
        if (j0 + 63 > q0 + w16 + 15 ? (j0 >= q0) : false) { }
        if (j0 >= q0) {
#pragma unroll
            for (int tt = 0; tt < 8; tt++) {
#pragma unroll
                for (int e = 0; e < 4; e++) {
                    int col = j0 + tt * 8 + 2 * qt + (e & 1);
                    int row = q0 + w16 + grp + 8 * (e >> 1);
                    if (col > row) s[tt][e] = NEG_BIG;
                }
            }
        }

        // ---- online softmax (s is in log2e units) ----
        {
            float m0 = NEG_BIG, m1 = NEG_BIG;
#pragma unroll
            for (int tt = 0; tt < 8; tt++) {
                m0 = fmaxf(m0, fmaxf(s[tt][0], s[tt][1]));
                m1 = fmaxf(m1, fmaxf(s[tt][2], s[tt][3]));
            }
            m0 = fmaxf(m0, __shfl_xor_sync(0xffffffffu, m0, 1));
            m0 = fmaxf(m0, __shfl_xor_sync(0xffffffffu, m0, 2));
            m1 = fmaxf(m1, __shfl_xor_sync(0xffffffffu, m1, 1));
            m1 = fmaxf(m1, __shfl_xor_sync(0xffffffffu, m1, 2));
            float nm0 = fmaxf(run_m0, m0), nm1 = fmaxf(run_m1, m1);
            float cr0 = ex2(run_m0 - nm0), cr1 = ex2(run_m1 - nm1);
            run_m0 = nm0; run_m1 = nm1;

            float sum0 = 0.f, sum1 = 0.f;
#pragma unroll
            for (int tt = 0; tt < 8; tt++) {
                s[tt][0] = ex2(s[tt][0] - nm0); sum0 += s[tt][0];
                s[tt][1] = ex2(s[tt][1] - nm0); sum0 += s[tt][1];
                s[tt][2] = ex2(s[tt][2] - nm1); sum1 += s[tt][2];
                s[tt][3] = ex2(s[tt][3] - nm1); sum1 += s[tt][3];
            }
            sum0 += __shfl_xor_sync(0xffffffffu, sum0, 1);
            sum0 += __shfl_xor_sync(0xffffffffu, sum0, 2);
            sum1 += __shfl_xor_sync(0xffffffffu, sum1, 1);
            sum1 += __shfl_xor_sync(0xffffffffu, sum1, 2);
            run_l0 = run_l0 * cr0 + sum0;
            run_l1 = run_l1 * cr1 + sum1;

#pragma unroll
            for (int tt = 0; tt < 16; tt++) {
                o[tt][0] *= cr0; o[tt][1] *= cr0;
                o[tt][2] *= cr1; o[tt][3] *= cr1;
            }
        }

        // ---- O += P V (bf16x3; P from accumulator registers) ----
        const uint32_t vh = FVH(buf), vl = FVL(buf);
#pragma unroll
        for (int k = 0; k < 4; k++) {
            uint32_t ph[4], pl[4];
            packsplit(s[2 * k][0],     s[2 * k][1],     ph[0], pl[0]);
            packsplit(s[2 * k][2],     s[2 * k][3],     ph[1], pl[1]);
            packsplit(s[2 * k + 1][0], s[2 * k + 1][1], ph[2], pl[2]);
            packsplit(s[2 * k + 1][2], s[2 * k + 1][3], ph[3], pl[3]);
#pragma unroll
            for (int nb = 0; nb < 8; nb++) {
                uint32_t bh[4], bl[4];
                uint32_t voff = (uint32_t)((nb * 16 + b_row) * 72 + k * 16 + b_col) * 2;
                ldsm4(bh, sb + vh + voff);
                ldsm4(bl, sb + vl + voff);
#pragma unroll
                for (int hf = 0; hf < 2; hf++) {
                    float* c = o[nb * 2 + hf];
                    mma16(c, ph, &bl[hf * 2]);
                    mma16(c, pl, &bh[hf * 2]);
                    mma16(c, ph, &bh[hf * 2]);
                }
            }
        }
        __syncthreads();
    }

    // ---- epilogue ----
    {
        float inv0 = 1.f / run_l0;
        float inv1 = 1.f / run_l1;
        int row0 = q0 + w16 + grp;
        float* p0 = O + (((size_t)b * Sn + row0) * Hn + h) * 128 + 2 * qt;
        float* p1 = O + (((size_t)b * Sn + row0 + 8) * Hn + h) * 128 + 2 * qt;
#pragma unroll
        for (int tt = 0; tt < 16; tt++) {
            *(float2*)(p0 + tt * 8) = make_float2(o[tt][0] * inv0, o[tt][1] * inv0);
            *(float2*)(p1 + tt * 8) = make_float2(o[tt][2] * inv1, o[tt][3] * inv1);
        }
    }
}

// ---------------------------------------------------------------------------
extern "C" void kernel_launch(void* const* d_in, const int* in_sizes, int n_in,
                              void* d_out, int out_size)
{
    const float* x    = (const float*)d_in[0];
    const float* mask = (const float*)d_in[1];
    const float* Wp[4] = {(const float*)d_in[2], (const float*)d_in[6],
                          (const float*)d_in[10], (const float*)d_in[14]};
    const float* bp[4] = {(const float*)d_in[3], (const float*)d_in[7],
                          (const float*)d_in[11], (const float*)d_in[15]};
    const float* Ap[4] = {(const float*)d_in[4], (const float*)d_in[8],
                          (const float*)d_in[12], (const float*)d_in[16]};
    const float* Bp[4] = {(const float*)d_in[5], (const float*)d_in[9],
                          (const float*)d_in[13], (const float*)d_in[17]};
    float* out = (float*)d_out;

    float *gq, *gk, *gv, *go;
    cudaGetSymbolAddress((void**)&gq, g_q);
    cudaGetSymbolAddress((void**)&gk, g_k);
    cudaGetSymbolAddress((void**)&gv, g_v);
    cudaGetSymbolAddress((void**)&go, g_o);
    float* gqkv[3] = {gq, gk, gv};

    float* gh[3];
    __nv_bfloat16 *xhi, *xlo, *ohi, *olo;
    __nv_bfloat16 *Whi[4], *Wlo[4], *AXhi[4], *AXlo[4], *BXhi[4], *BXlo[4];
    __nv_bfloat16 *hhi[3], *hlo[3];
    __nv_bfloat16 *qshi, *qslo, *kshi, *kslo, *vthi, *vtlo;
    {
        char *p;
        cudaGetSymbolAddress((void**)&p, g_h);
        for (int i = 0; i < 3; i++) gh[i] = (float*)(p + (size_t)i * Mn * 128 * 4);
        cudaGetSymbolAddress((void**)&p, g_xhi); xhi = (__nv_bfloat16*)p;
        cudaGetSymbolAddress((void**)&p, g_xlo); xlo = (__nv_bfloat16*)p;
        cudaGetSymbolAddress((void**)&p, g_ohi); ohi = (__nv_bfloat16*)p;
        cudaGetSymbolAddress((void**)&p, g_olo); olo = (__nv_bfloat16*)p;
        cudaGetSymbolAddress((void**)&p, g_qshi); qshi = (__nv_bfloat16*)p;
        cudaGetSymbolAddress((void**)&p, g_qslo); qslo = (__nv_bfloat16*)p;
        cudaGetSymbolAddress((void**)&p, g_kshi); kshi = (__nv_bfloat16*)p;
        cudaGetSymbolAddress((void**)&p, g_kslo); kslo = (__nv_bfloat16*)p;
        cudaGetSymbolAddress((void**)&p, g_vthi); vthi = (__nv_bfloat16*)p;
        cudaGetSymbolAddress((void**)&p, g_vtlo); vtlo = (__nv_bfloat16*)p;
        char *p_Wh, *p_Wl, *p_Ah, *p_Al, *p_Bh, *p_Bl, *p_hh, *p_hl;
        cudaGetSymbolAddress((void**)&p_Wh, g_Whi);
        cudaGetSymbolAddress((void**)&p_Wl, g_Wlo);
        cudaGetSymbolAddress((void**)&p_Ah, g_AXhi);
        cudaGetSymbolAddress((void**)&p_Al, g_AXlo);
        cudaGetSymbolAddress((void**)&p_Bh, g_BXhi);
        cudaGetSymbolAddress((void**)&p_Bl, g_BXlo);
        cudaGetSymbolAddress((void**)&p_hh, g_hhi);
        cudaGetSymbolAddress((void**)&p_hl, g_hlo);
        for (int i = 0; i < 3; i++) {
            hhi[i] = (__nv_bfloat16*)(p_hh + (size_t)i * Mn * 128 * 2);
            hlo[i] = (__nv_bfloat16*)(p_hl + (size_t)i * Mn * 128 * 2);
        }
        for (int i = 0; i < 4; i++) {
            Whi[i]  = (__nv_bfloat16*)(p_Wh + (size_t)i * HDn * En * 2);
            Wlo[i]  = (__nv_bfloat16*)(p_Wl + (size_t)i * HDn * En * 2);
            AXhi[i] = (__nv_bfloat16*)(p_Ah + (size_t)i * 128 * En * 2);
            AXlo[i] = (__nv_bfloat16*)(p_Al + (size_t)i * 128 * En * 2);
            BXhi[i] = (__nv_bfloat16*)(p_Bh + (size_t)i * HDn * 128 * 2);
            BXlo[i] = (__nv_bfloat16*)(p_Bl + (size_t)i * HDn * 128 * 2);
        }
    }

    KernT tg_d = tgemm2_kernel<128, 128, 2, 8, 8>;
    KernT tg_h = tgemm2_kernel<32, 128, 1, 8, 4>;
    cudaFuncSetAttribute(tg_d, cudaFuncAttributeMaxDynamicSharedMemorySize, DENSE_SMEM);
    cudaFuncSetAttribute(tg_h, cudaFuncAttributeMaxDynamicSharedMemorySize, H_SMEM);
    cudaFuncSetAttribute(flash_kernel, cudaFuncAttributeMaxDynamicSharedMemorySize, FLASH_SMEM);

    auto cvt = [&](const float* s, __nv_bfloat16* h, __nv_bfloat16* l, size_t n) {
        int n4 = (int)(n / 4);
        cvt_kernel<<<(n4 + 255) / 256, 256>>>(s, h, l, n4);
    };

    // ---- conversions ----
    cvt(x, xhi, xlo, (size_t)Mn * En);
    for (int i = 0; i < 4; i++) {
        cvt(Wp[i], Whi[i], Wlo[i], (size_t)HDn * En);
        cvt(Ap[i], AXhi[i], AXlo[i], (size_t)128 * En);
        cvt(Bp[i], BXhi[i], BXlo[i], (size_t)HDn * 128);
    }

    GArgs a;
    // ---- h projections (q,k,v) ----
    for (int i = 0; i < 3; i++) {
        a.Ahi[i] = xhi; a.Alo[i] = xlo;
        a.Bhi[i] = AXhi[i]; a.Blo[i] = AXlo[i];
        a.bias[i] = nullptr; a.mask[i] = mask; a.C[i] = gh[i];
    }
    tg_h<<<dim3(1, Mn / 32, 3), 128, H_SMEM>>>(a, Mn, 128, En, 0);
    for (int i = 0; i < 3; i++) cvt(gh[i], hhi[i], hlo[i], (size_t)Mn * 128);

    // ---- dense q,k,v ----
    for (int i = 0; i < 3; i++) {
        a.Ahi[i] = xhi; a.Alo[i] = xlo;
        a.Bhi[i] = Whi[i]; a.Blo[i] = Wlo[i];
        a.bias[i] = bp[i]; a.mask[i] = nullptr; a.C[i] = gqkv[i];
    }
    tg_d<<<dim3(HDn / 128, Mn / 128, 3), 256, DENSE_SMEM>>>(a, Mn, HDn, En, 0);

    // ---- low-rank B accumulate q,k,v ----
    for (int i = 0; i < 3; i++) {
        a.Ahi[i] = hhi[i]; a.Alo[i] = hlo[i];
        a.Bhi[i] = BXhi[i]; a.Blo[i] = BXlo[i];
        a.bias[i] = nullptr; a.mask[i] = nullptr; a.C[i] = gqkv[i];
    }
    tg_d<<<dim3(HDn / 128, Mn / 128, 3), 256, DENSE_SMEM>>>(a, Mn, HDn, 128, 1);

    // ---- RoPE + split (q,k); V split+transpose ----
    {
        int total = Bn * Sn * Hn * (Dn / 2);
        rope_split_kernel<<<(total + 255) / 256, 256>>>(gq, gk, qshi, qslo, kshi, kslo);
        vsplit_kernel<<<dim3(Sn / 32, Dn / 32, Bn * Hn), dim3(32, 8)>>>(gv, vthi, vtlo);
    }

    // ---- Attention (tensor cores) ----
    flash_kernel<<<dim3(Sn / 128, Hn, Bn), 256, FLASH_SMEM>>>(
        qshi, qslo, kshi, kslo, vthi, vtlo, go);

    // ---- Output projection ----
    cvt(go, ohi, olo, (size_t)Mn * HDn);
    a.Ahi[0] = ohi; a.Alo[0] = olo;
    a.Bhi[0] = AXhi[3]; a.Blo[0] = AXlo[3];
    a.bias[0] = nullptr; a.mask[0] = mask; a.C[0] = gh[0];
    tg_h<<<dim3(1, Mn / 32, 1), 128, H_SMEM>>>(a, Mn, 128, HDn, 0);
    cvt(gh[0], hhi[0], hlo[0], (size_t)Mn * 128);

    a.Ahi[0] = ohi; a.Alo[0] = olo;
    a.Bhi[0] = Whi[3]; a.Blo[0] = Wlo[3];
    a.bias[0] = bp[3]; a.mask[0] = nullptr; a.C[0] = out;
    tg_d<<<dim3(En / 128, Mn / 128, 1), 256, DENSE_SMEM>>>(a, Mn, En, HDn, 0);

    a.Ahi[0] = hhi[0]; a.Alo[0] = hlo[0];
    a.Bhi[0] = BXhi[3]; a.Blo[0] = BXlo[3];
    a.bias[0] = nullptr; a.mask[0] = nullptr; a.C[0] = out;
    tg_d<<<dim3(En / 128, Mn / 128, 1), 256, DENSE_SMEM>>>(a, Mn, En, 128, 1);
}